// round 1
// baseline (speedup 1.0000x reference)
#include <cuda_runtime.h>
#include <math.h>

#define BATCH 2
#define SEQ   2048
#define HID   2048
#define NH    16
#define HD    128
#define MROWS (BATCH*SEQ)   // 4096

// -------- scratch (static device globals: no allocation allowed) ----------
__device__ float g_q[BATCH*NH*SEQ*HD];      // 33.5 MB  [b][h][s][d], rope applied
__device__ float g_k[BATCH*NH*SEQ*HD];      // 33.5 MB
__device__ float g_v[BATCH*NH*SEQ*HD];      // 33.5 MB
__device__ float g_att[MROWS*HID];          // 33.5 MB  [b*S+s][h*hd+d]
__device__ float g_sin[SEQ*HD];
__device__ float g_cos[SEQ*HD];

// -------- RoPE table: replicate jax fp32 rounding of pos*inv_freq ---------
__global__ void rope_table_kernel() {
    int idx = blockIdx.x * blockDim.x + threadIdx.x;
    if (idx >= SEQ*HD) return;
    int s = idx >> 7;
    int d = idx & 127;
    int j = d >> 1;
    // inv_freq = 10000^(-2j/128), computed in fp64 then rounded to fp32
    // (matches jnp.power result); angle computed as fp32 multiply like jnp.
    float inv = (float)exp(-2.0 * (double)j / 128.0 * log(10000.0));
    float ang = (float)s * inv;           // fp32 product, same rounding as ref
    g_sin[idx] = (float)sin((double)ang);
    g_cos[idx] = (float)cos((double)ang);
}

// -------- SGEMM: C = A[M,K] @ B[K,N] + bias, with fused epilogues ---------
// MODE 0: plain row-major store to C (M x N)
// MODE 1: permuted store to [b][h][s][d] with RoPE (Q/K projections)
// MODE 2: permuted store, no RoPE (V projection)
// BM=BN=128, BK=8, 256 threads, 8x8 microtile.
template<int MODE>
__global__ __launch_bounds__(256, 2) void sgemm_kernel(
    const float* __restrict__ A, const float* __restrict__ Bm,
    const float* __restrict__ bias, float* __restrict__ C,
    int N, int K)
{
    __shared__ float As[8][128];   // [k][m]
    __shared__ float Bs[8][128];   // [k][n]

    const int tid = threadIdx.x;
    const int m0 = blockIdx.y * 128;
    const int n0 = blockIdx.x * 128;

    const int arow = tid >> 1;          // 0..127
    const int acol = (tid & 1) * 4;     // 0 or 4
    const int brow = tid >> 5;          // 0..7
    const int bcol = (tid & 31) * 4;    // 0..124

    const int ty = tid >> 4;            // 0..15
    const int tx = tid & 15;            // 0..15

    float acc[8][8];
    #pragma unroll
    for (int i = 0; i < 8; i++)
        #pragma unroll
        for (int j = 0; j < 8; j++) acc[i][j] = 0.0f;

    const float* Ap = A + (size_t)(m0 + arow) * K + acol;
    const float* Bp = Bm + (size_t)brow * N + n0 + bcol;

    for (int k0 = 0; k0 < K; k0 += 8) {
        float4 av = *(const float4*)(Ap + k0);
        float4 bv = *(const float4*)(Bp + (size_t)k0 * N);
        As[acol + 0][arow] = av.x;
        As[acol + 1][arow] = av.y;
        As[acol + 2][arow] = av.z;
        As[acol + 3][arow] = av.w;
        *(float4*)&Bs[brow][bcol] = bv;
        __syncthreads();

        #pragma unroll
        for (int kk = 0; kk < 8; kk++) {
            float a[8], b[8];
            *(float4*)(a)     = *(const float4*)&As[kk][ty * 8];
            *(float4*)(a + 4) = *(const float4*)&As[kk][ty * 8 + 4];
            *(float4*)(b)     = *(const float4*)&Bs[kk][tx * 8];
            *(float4*)(b + 4) = *(const float4*)&Bs[kk][tx * 8 + 4];
            #pragma unroll
            for (int i = 0; i < 8; i++)
                #pragma unroll
                for (int j = 0; j < 8; j++)
                    acc[i][j] += a[i] * b[j];
        }
        __syncthreads();
    }

    // Epilogue
    if (MODE == 0) {
        #pragma unroll
        for (int i = 0; i < 8; i++) {
            int m = m0 + ty * 8 + i;
            float* cp = C + (size_t)m * N + n0 + tx * 8;
            float4 o0, o1;
            int nb = n0 + tx * 8;
            o0.x = acc[i][0] + bias[nb + 0];
            o0.y = acc[i][1] + bias[nb + 1];
            o0.z = acc[i][2] + bias[nb + 2];
            o0.w = acc[i][3] + bias[nb + 3];
            o1.x = acc[i][4] + bias[nb + 4];
            o1.y = acc[i][5] + bias[nb + 5];
            o1.z = acc[i][6] + bias[nb + 6];
            o1.w = acc[i][7] + bias[nb + 7];
            *(float4*)cp = o0;
            *(float4*)(cp + 4) = o1;
        }
    } else {
        #pragma unroll
        for (int i = 0; i < 8; i++) {
            int m = m0 + ty * 8 + i;
            int b = m >> 11;           // / SEQ
            int s = m & (SEQ - 1);
            #pragma unroll
            for (int j = 0; j < 8; j += 2) {
                int n = n0 + tx * 8 + j;
                int h = n >> 7;
                int d = n & 127;       // even
                float v0 = acc[i][j]     + bias[n];
                float v1 = acc[i][j + 1] + bias[n + 1];
                if (MODE == 1) {
                    float sn = g_sin[s * HD + d];
                    float cs = g_cos[s * HD + d];
                    float o0 = v0 * cs - v1 * sn;
                    float o1 = v1 * cs + v0 * sn;
                    v0 = o0; v1 = o1;
                }
                size_t oidx = ((size_t)((b * NH + h) * SEQ + s)) * HD + d;
                C[oidx]     = v0;
                C[oidx + 1] = v1;
            }
        }
    }
}

// -------- Flash attention: fp32, Br=Bc=64, hd=128 -------------------------
// grid (S/64, NH, B), 256 threads, dynamic smem.
// smem floats: Qt[128][65] | Kt[128][65] | Vs[64][128] | Ps[64][65] | m/l/f[64]
#define SM_QT   0
#define SM_KT   (128*65)
#define SM_VS   (SM_KT + 128*65)
#define SM_PS   (SM_VS + 64*128)
#define SM_M    (SM_PS + 64*65)
#define SM_L    (SM_M + 64)
#define SM_F    (SM_L + 64)
#define SM_TOT  (SM_F + 64)
#define SMEM_ATTN_BYTES (SM_TOT * 4)

__global__ __launch_bounds__(256, 1) void attn_kernel() {
    extern __shared__ float sm[];
    float* Qt   = sm + SM_QT;
    float* Kt   = sm + SM_KT;
    float* Vs   = sm + SM_VS;
    float* Ps   = sm + SM_PS;
    float* mrow = sm + SM_M;
    float* lrow = sm + SM_L;
    float* frow = sm + SM_F;

    const int tid = threadIdx.x;
    const int q0  = blockIdx.x * 64;
    const int h   = blockIdx.y;
    const int b   = blockIdx.z;

    const size_t bh_off = (size_t)(b * NH + h) * SEQ * HD;
    const float* qg = g_q + bh_off;
    const float* kg = g_k + bh_off;
    const float* vg = g_v + bh_off;

    // Load Q tile transposed: Qt[d][r]
    #pragma unroll
    for (int t = 0; t < 8; t++) {
        int lin = (t * 256 + tid) * 4;
        int r = lin >> 7;
        int d = lin & 127;
        float4 v = *(const float4*)(qg + (size_t)(q0 + r) * HD + d);
        Qt[(d + 0) * 65 + r] = v.x;
        Qt[(d + 1) * 65 + r] = v.y;
        Qt[(d + 2) * 65 + r] = v.z;
        Qt[(d + 3) * 65 + r] = v.w;
    }
    if (tid < 64) { mrow[tid] = -INFINITY; lrow[tid] = 0.0f; }

    const int ty = tid >> 4;     // 0..15
    const int tx = tid & 15;     // 0..15
    const int r0 = ty * 4;       // S rows / O rows
    const int c0 = tx * 4;       // S cols
    const int oc = tx * 8;       // O cols

    float oacc[4][8];
    #pragma unroll
    for (int i = 0; i < 4; i++)
        #pragma unroll
        for (int j = 0; j < 8; j++) oacc[i][j] = 0.0f;

    const float scale = 0.08838834764831845f;   // 1/sqrt(128)

    for (int kv0 = 0; kv0 < SEQ; kv0 += 64) {
        __syncthreads();   // prior iteration done with Kt/Vs/Ps; Q/m/l visible
        // Load K transposed + V direct
        #pragma unroll
        for (int t = 0; t < 8; t++) {
            int lin = (t * 256 + tid) * 4;
            int r = lin >> 7;
            int d = lin & 127;
            float4 kvv = *(const float4*)(kg + (size_t)(kv0 + r) * HD + d);
            Kt[(d + 0) * 65 + r] = kvv.x;
            Kt[(d + 1) * 65 + r] = kvv.y;
            Kt[(d + 2) * 65 + r] = kvv.z;
            Kt[(d + 3) * 65 + r] = kvv.w;
            float4 vvv = *(const float4*)(vg + (size_t)(kv0 + r) * HD + d);
            *(float4*)&Vs[r * 128 + d] = vvv;
        }
        __syncthreads();

        // S = Q K^T (scaled) -> Ps
        float sacc[4][4];
        #pragma unroll
        for (int i = 0; i < 4; i++)
            #pragma unroll
            for (int j = 0; j < 4; j++) sacc[i][j] = 0.0f;
        #pragma unroll 4
        for (int d = 0; d < 128; d++) {
            float qv[4], kv[4];
            #pragma unroll
            for (int i = 0; i < 4; i++) qv[i] = Qt[d * 65 + r0 + i];
            #pragma unroll
            for (int j = 0; j < 4; j++) kv[j] = Kt[d * 65 + c0 + j];
            #pragma unroll
            for (int i = 0; i < 4; i++)
                #pragma unroll
                for (int j = 0; j < 4; j++)
                    sacc[i][j] += qv[i] * kv[j];
        }
        #pragma unroll
        for (int i = 0; i < 4; i++)
            #pragma unroll
            for (int j = 0; j < 4; j++)
                Ps[(r0 + i) * 65 + c0 + j] = sacc[i][j] * scale;
        __syncthreads();

        // Online softmax per row (64 worker threads)
        if (tid < 64) {
            int r = tid;
            float mold = mrow[r];
            float mx = -INFINITY;
            #pragma unroll 8
            for (int c = 0; c < 64; c++) mx = fmaxf(mx, Ps[r * 65 + c]);
            float mnew = fmaxf(mold, mx);
            float fac = __expf(mold - mnew);    // 0 on first tile
            float l = lrow[r] * fac;
            #pragma unroll 8
            for (int c = 0; c < 64; c++) {
                float p = __expf(Ps[r * 65 + c] - mnew);
                Ps[r * 65 + c] = p;
                l += p;
            }
            mrow[r] = mnew;
            lrow[r] = l;
            frow[r] = fac;
        }
        __syncthreads();

        // O = O*fac + P @ V
        #pragma unroll
        for (int i = 0; i < 4; i++) {
            float f = frow[r0 + i];
            #pragma unroll
            for (int j = 0; j < 8; j++) oacc[i][j] *= f;
        }
        #pragma unroll 2
        for (int jj = 0; jj < 64; jj++) {
            float p[4];
            #pragma unroll
            for (int i = 0; i < 4; i++) p[i] = Ps[(r0 + i) * 65 + jj];
            float4 va = *(const float4*)&Vs[jj * 128 + oc];
            float4 vb = *(const float4*)&Vs[jj * 128 + oc + 4];
            #pragma unroll
            for (int i = 0; i < 4; i++) {
                oacc[i][0] += p[i] * va.x;
                oacc[i][1] += p[i] * va.y;
                oacc[i][2] += p[i] * va.z;
                oacc[i][3] += p[i] * va.w;
                oacc[i][4] += p[i] * vb.x;
                oacc[i][5] += p[i] * vb.y;
                oacc[i][6] += p[i] * vb.z;
                oacc[i][7] += p[i] * vb.w;
            }
        }
    }

    // Normalize and store into (B,S,H) row-major layout for the O-projection.
    #pragma unroll
    for (int i = 0; i < 4; i++) {
        int r = r0 + i;
        float inv_l = 1.0f / lrow[r];
        size_t base = ((size_t)(b * SEQ + q0 + r)) * HID + h * HD + oc;
        float4 o0, o1;
        o0.x = oacc[i][0] * inv_l;
        o0.y = oacc[i][1] * inv_l;
        o0.z = oacc[i][2] * inv_l;
        o0.w = oacc[i][3] * inv_l;
        o1.x = oacc[i][4] * inv_l;
        o1.y = oacc[i][5] * inv_l;
        o1.z = oacc[i][6] * inv_l;
        o1.w = oacc[i][7] * inv_l;
        *(float4*)(g_att + base)     = o0;
        *(float4*)(g_att + base + 4) = o1;
    }
}

// ---------------------------------------------------------------------------
extern "C" void kernel_launch(void* const* d_in, const int* in_sizes, int n_in,
                              void* d_out, int out_size) {
    const float* X  = (const float*)d_in[0];
    const float* Wq = (const float*)d_in[1];
    const float* bq = (const float*)d_in[2];
    const float* Wk = (const float*)d_in[3];
    const float* bk = (const float*)d_in[4];
    const float* Wv = (const float*)d_in[5];
    const float* bv = (const float*)d_in[6];
    const float* Wo = (const float*)d_in[7];
    const float* bo = (const float*)d_in[8];
    float* out = (float*)d_out;

    float *q, *k, *v, *att;
    cudaGetSymbolAddress((void**)&q,   g_q);
    cudaGetSymbolAddress((void**)&k,   g_k);
    cudaGetSymbolAddress((void**)&v,   g_v);
    cudaGetSymbolAddress((void**)&att, g_att);

    cudaFuncSetAttribute(attn_kernel,
                         cudaFuncAttributeMaxDynamicSharedMemorySize,
                         SMEM_ATTN_BYTES);

    rope_table_kernel<<<(SEQ * HD + 255) / 256, 256>>>();

    dim3 gg(HID / 128, MROWS / 128);
    sgemm_kernel<1><<<gg, 256>>>(X, Wq, bq, q, HID, HID);   // Q proj + rope
    sgemm_kernel<1><<<gg, 256>>>(X, Wk, bk, k, HID, HID);   // K proj + rope
    sgemm_kernel<2><<<gg, 256>>>(X, Wv, bv, v, HID, HID);   // V proj

    attn_kernel<<<dim3(SEQ / 64, NH, BATCH), 256, SMEM_ATTN_BYTES>>>();

    sgemm_kernel<0><<<gg, 256>>>(att, Wo, bo, out, HID, HID); // O proj
}

// round 2
// speedup vs baseline: 3.1309x; 3.1309x over previous
#include <cuda_runtime.h>
#include <math.h>

#define BATCH 2
#define SEQ   2048
#define HID   2048
#define NH    16
#define HD    128
#define MROWS (BATCH*SEQ)   // 4096

// -------- scratch (static device globals) ---------------------------------
__device__ float g_q[BATCH*NH*SEQ*HD];
__device__ float g_k[BATCH*NH*SEQ*HD];
__device__ float g_v[BATCH*NH*SEQ*HD];
__device__ float g_att[MROWS*HID];
__device__ float g_sin[SEQ*HD];
__device__ float g_cos[SEQ*HD];

// -------- helpers ----------------------------------------------------------
__device__ __forceinline__ unsigned f2tf(float x) {
    unsigned r;
    asm("cvt.rna.tf32.f32 %0, %1;" : "=r"(r) : "f"(x));
    return r;
}

__device__ __forceinline__ void mma_tf32(float* d, const unsigned* a, const unsigned* b) {
    asm volatile(
        "mma.sync.aligned.m16n8k8.row.col.f32.tf32.tf32.f32 "
        "{%0,%1,%2,%3}, {%4,%5,%6,%7}, {%8,%9}, {%0,%1,%2,%3};"
        : "+f"(d[0]), "+f"(d[1]), "+f"(d[2]), "+f"(d[3])
        : "r"(a[0]), "r"(a[1]), "r"(a[2]), "r"(a[3]), "r"(b[0]), "r"(b[1]));
}

// -------- RoPE table -------------------------------------------------------
__global__ void rope_table_kernel() {
    int idx = blockIdx.x * blockDim.x + threadIdx.x;
    if (idx >= SEQ*HD) return;
    int s = idx >> 7;
    int d = idx & 127;
    int j = d >> 1;
    float inv = (float)exp(-2.0 * (double)j / 128.0 * log(10000.0));
    float ang = (float)s * inv;
    g_sin[idx] = (float)sin((double)ang);
    g_cos[idx] = (float)cos((double)ang);
}

// -------- TF32 tensor-core GEMM: C = A[M,K]@B[K,N] + bias ------------------
// MODE 0: plain row-major store; MODE 1: [b][h][s][d] permute + RoPE;
// MODE 2: permute only. BM=BN=128, BK=16, 256 threads, 8 warps (2x4),
// warp tile 64x32 via m16n8k8 (4 mtiles x 4 ntiles).
#define AS_STRIDE 20     // words; banks 20g+c -> conflict-free frag loads
#define BS_STRIDE 136    // words; banks 8c+g  -> conflict-free frag loads

template<int MODE>
__global__ __launch_bounds__(256, 2) void gemm_tc_kernel(
    const float* __restrict__ A, const float* __restrict__ Bm,
    const float* __restrict__ bias, float* __restrict__ C,
    int N, int K)
{
    __shared__ unsigned As[128 * AS_STRIDE];   // [m][k] tf32 bits
    __shared__ unsigned Bs[16 * BS_STRIDE];    // [k][n] tf32 bits

    const int t    = threadIdx.x;
    const int wid  = t >> 5;
    const int lane = t & 31;
    const int g    = lane >> 2;   // group id
    const int c    = lane & 3;    // thread-in-group
    const int wrow = wid >> 2;    // 0..1
    const int wcol = wid & 3;     // 0..3
    const int m0 = blockIdx.y * 128;
    const int n0 = blockIdx.x * 128;

    // A tile loaders: row = t>>1 (0..127), 8 cols at (t&1)*8
    const int arow = t >> 1;
    const int acol = (t & 1) * 8;
    // B tile loaders: rows t>>5 and +8, cols lane*4
    const int brow = t >> 5;
    const int bcol = lane * 4;

    const float* Ap = A + (size_t)(m0 + arow) * K + acol;
    const float* Bp = Bm + (size_t)brow * N + n0 + bcol;

    float acc[4][4][4];
    #pragma unroll
    for (int i = 0; i < 4; i++)
        #pragma unroll
        for (int j = 0; j < 4; j++)
            #pragma unroll
            for (int r = 0; r < 4; r++) acc[i][j][r] = 0.0f;

    float4 pa0, pa1, pb0, pb1;

    // prologue: tile 0
    pa0 = *(const float4*)(Ap);
    pa1 = *(const float4*)(Ap + 4);
    pb0 = *(const float4*)(Bp);
    pb1 = *(const float4*)(Bp + (size_t)8 * N);
    {
        unsigned* asp = &As[arow * AS_STRIDE + acol];
        asp[0]=f2tf(pa0.x); asp[1]=f2tf(pa0.y); asp[2]=f2tf(pa0.z); asp[3]=f2tf(pa0.w);
        asp[4]=f2tf(pa1.x); asp[5]=f2tf(pa1.y); asp[6]=f2tf(pa1.z); asp[7]=f2tf(pa1.w);
        unsigned* bsp0 = &Bs[brow * BS_STRIDE + bcol];
        unsigned* bsp1 = &Bs[(brow + 8) * BS_STRIDE + bcol];
        bsp0[0]=f2tf(pb0.x); bsp0[1]=f2tf(pb0.y); bsp0[2]=f2tf(pb0.z); bsp0[3]=f2tf(pb0.w);
        bsp1[0]=f2tf(pb1.x); bsp1[1]=f2tf(pb1.y); bsp1[2]=f2tf(pb1.z); bsp1[3]=f2tf(pb1.w);
    }
    __syncthreads();

    for (int k0 = 0; k0 < K; k0 += 16) {
        const bool more = (k0 + 16) < K;
        if (more) {
            pa0 = *(const float4*)(Ap + k0 + 16);
            pa1 = *(const float4*)(Ap + k0 + 20);
            pb0 = *(const float4*)(Bp + (size_t)(k0 + 16) * N);
            pb1 = *(const float4*)(Bp + (size_t)(k0 + 24) * N);
        }

        #pragma unroll
        for (int ks = 0; ks < 2; ks++) {
            const int kb = ks * 8;
            unsigned a[4][4];
            #pragma unroll
            for (int mt = 0; mt < 4; mt++) {
                const int mb = wrow * 64 + mt * 16;
                a[mt][0] = As[(mb + g)     * AS_STRIDE + kb + c];
                a[mt][1] = As[(mb + g + 8) * AS_STRIDE + kb + c];
                a[mt][2] = As[(mb + g)     * AS_STRIDE + kb + c + 4];
                a[mt][3] = As[(mb + g + 8) * AS_STRIDE + kb + c + 4];
            }
            #pragma unroll
            for (int nt = 0; nt < 4; nt++) {
                const int nb = wcol * 32 + nt * 8 + g;
                unsigned b[2];
                b[0] = Bs[(kb + c)     * BS_STRIDE + nb];
                b[1] = Bs[(kb + c + 4) * BS_STRIDE + nb];
                #pragma unroll
                for (int mt = 0; mt < 4; mt++)
                    mma_tf32(acc[mt][nt], a[mt], b);
            }
        }

        if (more) {
            __syncthreads();
            unsigned* asp = &As[arow * AS_STRIDE + acol];
            asp[0]=f2tf(pa0.x); asp[1]=f2tf(pa0.y); asp[2]=f2tf(pa0.z); asp[3]=f2tf(pa0.w);
            asp[4]=f2tf(pa1.x); asp[5]=f2tf(pa1.y); asp[6]=f2tf(pa1.z); asp[7]=f2tf(pa1.w);
            unsigned* bsp0 = &Bs[brow * BS_STRIDE + bcol];
            unsigned* bsp1 = &Bs[(brow + 8) * BS_STRIDE + bcol];
            bsp0[0]=f2tf(pb0.x); bsp0[1]=f2tf(pb0.y); bsp0[2]=f2tf(pb0.z); bsp0[3]=f2tf(pb0.w);
            bsp1[0]=f2tf(pb1.x); bsp1[1]=f2tf(pb1.y); bsp1[2]=f2tf(pb1.z); bsp1[3]=f2tf(pb1.w);
            __syncthreads();
        }
    }

    // Epilogue: C fragment (mt,nt): rows mb+g, mb+g+8; cols nb+2c, nb+2c+1
    #pragma unroll
    for (int mt = 0; mt < 4; mt++) {
        #pragma unroll
        for (int nt = 0; nt < 4; nt++) {
            const int col = n0 + wcol * 32 + nt * 8 + 2 * c;
            #pragma unroll
            for (int half = 0; half < 2; half++) {
                const int row = m0 + wrow * 64 + mt * 16 + g + half * 8;
                float v0 = acc[mt][nt][half * 2 + 0] + bias[col];
                float v1 = acc[mt][nt][half * 2 + 1] + bias[col + 1];
                if (MODE == 0) {
                    float2 o = make_float2(v0, v1);
                    *(float2*)(C + (size_t)row * N + col) = o;
                } else {
                    const int b = row >> 11;
                    const int s = row & (SEQ - 1);
                    const int h = col >> 7;
                    const int d = col & 127;  // even
                    if (MODE == 1) {
                        float sn = g_sin[s * HD + d];
                        float cs = g_cos[s * HD + d];
                        float o0 = v0 * cs - v1 * sn;
                        float o1 = v1 * cs + v0 * sn;
                        v0 = o0; v1 = o1;
                    }
                    size_t oidx = ((size_t)((b * NH + h) * SEQ + s)) * HD + d;
                    float2 o = make_float2(v0, v1);
                    *(float2*)(&C[oidx]) = o;
                }
            }
        }
    }
}

// -------- Flash attention, TF32 tensor cores -------------------------------
// Br=128, Bc=64, hd=128, 512 threads (16 warps, 4x4 grid).
// S warp tile 32x16; PV warp tile 32x32.
#define QK_STRIDE 132   // words; banks 4g+c -> conflict-free
#define V_STRIDE  136   // words; banks 8c+g -> conflict-free
#define P_STRIDE  68    // words; banks 4g+c -> conflict-free

#define SM_QS 0
#define SM_KS (SM_QS + 128*QK_STRIDE)
#define SM_VS (SM_KS + 64*QK_STRIDE)
#define SM_PS (SM_VS + 64*V_STRIDE)
#define SM_M  (SM_PS + 128*P_STRIDE)
#define SM_L  (SM_M + 128)
#define SM_F  (SM_L + 128)
#define SM_TOT (SM_F + 128)
#define SMEM_ATTN_BYTES (SM_TOT * 4)

__global__ __launch_bounds__(512, 1) void attn_kernel() {
    extern __shared__ unsigned sm[];
    unsigned* Qs = sm + SM_QS;
    unsigned* Ks = sm + SM_KS;
    unsigned* Vs = sm + SM_VS;
    unsigned* Ps = sm + SM_PS;
    float* mrow = (float*)(sm + SM_M);
    float* lrow = (float*)(sm + SM_L);
    float* frow = (float*)(sm + SM_F);

    const int t    = threadIdx.x;
    const int wid  = t >> 5;
    const int lane = t & 31;
    const int g    = lane >> 2;
    const int c    = lane & 3;
    const int wrow = wid >> 2;    // 0..3 : 32 rows each
    const int wcol = wid & 3;     // 0..3

    const int q0 = blockIdx.x * 128;
    const int h  = blockIdx.y;
    const int b  = blockIdx.z;
    const size_t bh_off = (size_t)(b * NH + h) * SEQ * HD;
    const float* qg = g_q + bh_off;
    const float* kg = g_k + bh_off;
    const float* vg = g_v + bh_off;

    // Load Q tile (128 x 128), tf32-converted, stride QK_STRIDE
    #pragma unroll
    for (int i = 0; i < 8; i++) {
        int lin = (i * 512 + t) * 4;
        int r = lin >> 7;
        int d = lin & 127;
        float4 v = *(const float4*)(qg + (size_t)(q0 + r) * HD + d);
        unsigned* p = &Qs[r * QK_STRIDE + d];
        p[0]=f2tf(v.x); p[1]=f2tf(v.y); p[2]=f2tf(v.z); p[3]=f2tf(v.w);
    }
    if (t < 128) { mrow[t] = -INFINITY; lrow[t] = 0.0f; }

    float oacc[2][4][4];   // [mt][nt][frag]
    #pragma unroll
    for (int i = 0; i < 2; i++)
        #pragma unroll
        for (int j = 0; j < 4; j++)
            #pragma unroll
            for (int r = 0; r < 4; r++) oacc[i][j][r] = 0.0f;

    const float scale = 0.08838834764831845f;  // 1/sqrt(128)
    const int srow = t >> 2;   // softmax row (0..127)
    const int sseg = t & 3;    // 16-col segment

    for (int kv0 = 0; kv0 < SEQ; kv0 += 64) {
        __syncthreads();
        // Load K, V tiles (64 x 128)
        #pragma unroll
        for (int i = 0; i < 4; i++) {
            int lin = (i * 512 + t) * 4;
            int r = lin >> 7;
            int d = lin & 127;
            float4 kv = *(const float4*)(kg + (size_t)(kv0 + r) * HD + d);
            unsigned* kp = &Ks[r * QK_STRIDE + d];
            kp[0]=f2tf(kv.x); kp[1]=f2tf(kv.y); kp[2]=f2tf(kv.z); kp[3]=f2tf(kv.w);
            float4 vv = *(const float4*)(vg + (size_t)(kv0 + r) * HD + d);
            unsigned* vp = &Vs[r * V_STRIDE + d];
            vp[0]=f2tf(vv.x); vp[1]=f2tf(vv.y); vp[2]=f2tf(vv.z); vp[3]=f2tf(vv.w);
        }
        __syncthreads();

        // S = Q @ K^T over d (16 ksteps), warp tile 32x16
        float sacc[2][2][4];
        #pragma unroll
        for (int i = 0; i < 2; i++)
            #pragma unroll
            for (int j = 0; j < 2; j++)
                #pragma unroll
                for (int r = 0; r < 4; r++) sacc[i][j][r] = 0.0f;

        #pragma unroll 4
        for (int ks = 0; ks < 16; ks++) {
            const int kb = ks * 8;
            unsigned a[2][4];
            #pragma unroll
            for (int mt = 0; mt < 2; mt++) {
                const int mb = wrow * 32 + mt * 16;
                a[mt][0] = Qs[(mb + g)     * QK_STRIDE + kb + c];
                a[mt][1] = Qs[(mb + g + 8) * QK_STRIDE + kb + c];
                a[mt][2] = Qs[(mb + g)     * QK_STRIDE + kb + c + 4];
                a[mt][3] = Qs[(mb + g + 8) * QK_STRIDE + kb + c + 4];
            }
            #pragma unroll
            for (int nt = 0; nt < 2; nt++) {
                const int nb = wcol * 16 + nt * 8 + g;
                unsigned bb[2];
                bb[0] = Ks[nb * QK_STRIDE + kb + c];
                bb[1] = Ks[nb * QK_STRIDE + kb + c + 4];
                #pragma unroll
                for (int mt = 0; mt < 2; mt++)
                    mma_tf32(sacc[mt][nt], a[mt], bb);
            }
        }

        // Store scaled logits to Ps (fp32 bits for softmax)
        #pragma unroll
        for (int mt = 0; mt < 2; mt++) {
            #pragma unroll
            for (int nt = 0; nt < 2; nt++) {
                const int col = wcol * 16 + nt * 8 + 2 * c;
                #pragma unroll
                for (int half = 0; half < 2; half++) {
                    const int row = wrow * 32 + mt * 16 + g + half * 8;
                    float2 o = make_float2(sacc[mt][nt][half*2+0] * scale,
                                           sacc[mt][nt][half*2+1] * scale);
                    *(float2*)(&Ps[row * P_STRIDE + col]) = o;
                }
            }
        }
        __syncthreads();

        // Online softmax: 4 lanes per row, 16 cols each
        {
            float* prow = (float*)&Ps[srow * P_STRIDE + sseg * 16];
            float mold = mrow[srow];
            float mx = -INFINITY;
            #pragma unroll
            for (int i = 0; i < 16; i++) mx = fmaxf(mx, prow[i]);
            mx = fmaxf(mx, __shfl_xor_sync(0xffffffffu, mx, 1));
            mx = fmaxf(mx, __shfl_xor_sync(0xffffffffu, mx, 2));
            float mnew = fmaxf(mold, mx);
            float fac = __expf(mold - mnew);
            float psum = 0.0f;
            #pragma unroll
            for (int i = 0; i < 16; i++) {
                float p = __expf(prow[i] - mnew);
                p = __uint_as_float(f2tf(p));   // tf32-consistent with PV mma
                prow[i] = p;
                psum += p;
            }
            psum += __shfl_xor_sync(0xffffffffu, psum, 1);
            psum += __shfl_xor_sync(0xffffffffu, psum, 2);
            if (sseg == 0) {
                lrow[srow] = lrow[srow] * fac + psum;
                mrow[srow] = mnew;
                frow[srow] = fac;
            }
        }
        __syncthreads();

        // O = O*fac + P @ V ; warp tile 32x128-> (2 mtiles x 4 ntiles), 8 ksteps
        #pragma unroll
        for (int mt = 0; mt < 2; mt++) {
            const int mb = wrow * 32 + mt * 16;
            const float f1 = frow[mb + g];
            const float f2 = frow[mb + g + 8];
            #pragma unroll
            for (int nt = 0; nt < 4; nt++) {
                oacc[mt][nt][0] *= f1; oacc[mt][nt][1] *= f1;
                oacc[mt][nt][2] *= f2; oacc[mt][nt][3] *= f2;
            }
        }
        #pragma unroll 2
        for (int ks = 0; ks < 8; ks++) {
            const int kb = ks * 8;
            unsigned a[2][4];
            #pragma unroll
            for (int mt = 0; mt < 2; mt++) {
                const int mb = wrow * 32 + mt * 16;
                a[mt][0] = Ps[(mb + g)     * P_STRIDE + kb + c];
                a[mt][1] = Ps[(mb + g + 8) * P_STRIDE + kb + c];
                a[mt][2] = Ps[(mb + g)     * P_STRIDE + kb + c + 4];
                a[mt][3] = Ps[(mb + g + 8) * P_STRIDE + kb + c + 4];
            }
            #pragma unroll
            for (int nt = 0; nt < 4; nt++) {
                const int nb = wcol * 32 + nt * 8 + g;
                unsigned bb[2];
                bb[0] = Vs[(kb + c)     * V_STRIDE + nb];
                bb[1] = Vs[(kb + c + 4) * V_STRIDE + nb];
                #pragma unroll
                for (int mt = 0; mt < 2; mt++)
                    mma_tf32(oacc[mt][nt], a[mt], bb);
            }
        }
    }
    __syncthreads();

    // Normalize and store to (B,S,H) row-major for the O projection
    #pragma unroll
    for (int mt = 0; mt < 2; mt++) {
        #pragma unroll
        for (int half = 0; half < 2; half++) {
            const int row = wrow * 32 + mt * 16 + g + half * 8;
            const float invl = 1.0f / lrow[row];
            #pragma unroll
            for (int nt = 0; nt < 4; nt++) {
                const int col = wcol * 32 + nt * 8 + 2 * c;
                size_t base = ((size_t)(b * SEQ + q0 + row)) * HID + h * HD + col;
                float2 o = make_float2(oacc[mt][nt][half*2+0] * invl,
                                       oacc[mt][nt][half*2+1] * invl);
                *(float2*)(g_att + base) = o;
            }
        }
    }
}

// ---------------------------------------------------------------------------
extern "C" void kernel_launch(void* const* d_in, const int* in_sizes, int n_in,
                              void* d_out, int out_size) {
    const float* X  = (const float*)d_in[0];
    const float* Wq = (const float*)d_in[1];
    const float* bq = (const float*)d_in[2];
    const float* Wk = (const float*)d_in[3];
    const float* bk = (const float*)d_in[4];
    const float* Wv = (const float*)d_in[5];
    const float* bv = (const float*)d_in[6];
    const float* Wo = (const float*)d_in[7];
    const float* bo = (const float*)d_in[8];
    float* out = (float*)d_out;

    float *q, *k, *v, *att;
    cudaGetSymbolAddress((void**)&q,   g_q);
    cudaGetSymbolAddress((void**)&k,   g_k);
    cudaGetSymbolAddress((void**)&v,   g_v);
    cudaGetSymbolAddress((void**)&att, g_att);

    cudaFuncSetAttribute(attn_kernel,
                         cudaFuncAttributeMaxDynamicSharedMemorySize,
                         SMEM_ATTN_BYTES);

    rope_table_kernel<<<(SEQ * HD + 255) / 256, 256>>>();

    dim3 gg(HID / 128, MROWS / 128);
    gemm_tc_kernel<1><<<gg, 256>>>(X, Wq, bq, q, HID, HID);
    gemm_tc_kernel<1><<<gg, 256>>>(X, Wk, bk, k, HID, HID);
    gemm_tc_kernel<2><<<gg, 256>>>(X, Wv, bv, v, HID, HID);

    attn_kernel<<<dim3(SEQ / 128, NH, BATCH), 512, SMEM_ATTN_BYTES>>>();

    gemm_tc_kernel<0><<<gg, 256>>>(att, Wo, bo, out, HID, HID);
}

// round 4
// speedup vs baseline: 3.5217x; 1.1248x over previous
#include <cuda_runtime.h>
#include <math.h>
#include <stdint.h>

#define BATCH 2
#define SEQ   2048
#define HID   2048
#define NH    16
#define HD    128
#define MROWS (BATCH*SEQ)   // 4096

// -------- scratch (static device globals) ---------------------------------
__device__ float g_q[BATCH*NH*SEQ*HD];     // tf32 bits, rope applied
__device__ float g_k[BATCH*NH*SEQ*HD];
__device__ float g_v[BATCH*NH*SEQ*HD];
__device__ float g_att[MROWS*HID];         // tf32 bits
__device__ float g_xtf[MROWS*HID];         // X tf32 bits
__device__ float g_wq[HID*HID];            // W tf32 bits (layout unchanged [K,N])
__device__ float g_wk[HID*HID];
__device__ float g_wv[HID*HID];
__device__ float g_wo[HID*HID];
__device__ float g_sin[SEQ*HD];
__device__ float g_cos[SEQ*HD];

// -------- helpers ----------------------------------------------------------
__device__ __forceinline__ unsigned f2tf(float x) {
    unsigned r;
    asm("cvt.rna.tf32.f32 %0, %1;" : "=r"(r) : "f"(x));
    return r;
}

__device__ __forceinline__ void mma_tf32(float* d, const unsigned* a, const unsigned* b) {
    asm volatile(
        "mma.sync.aligned.m16n8k8.row.col.f32.tf32.tf32.f32 "
        "{%0,%1,%2,%3}, {%4,%5,%6,%7}, {%8,%9}, {%0,%1,%2,%3};"
        : "+f"(d[0]), "+f"(d[1]), "+f"(d[2]), "+f"(d[3])
        : "r"(a[0]), "r"(a[1]), "r"(a[2]), "r"(a[3]), "r"(b[0]), "r"(b[1]));
}

__device__ __forceinline__ uint32_t smem_u32(const void* p) {
    uint32_t a;
    asm("{ .reg .u64 t; cvta.to.shared.u64 t, %1; cvt.u32.u64 %0, t; }"
        : "=r"(a) : "l"(p));
    return a;
}

__device__ __forceinline__ void cpa16(uint32_t dst, const float* src) {
    asm volatile(
        "{ .reg .u64 ga; cvta.to.global.u64 ga, %1;"
        "  cp.async.cg.shared.global [%0], [ga], 16; }"
        :: "r"(dst), "l"(src) : "memory");
}
__device__ __forceinline__ void cpa_commit() {
    asm volatile("cp.async.commit_group;" ::: "memory");
}
__device__ __forceinline__ void cpa_wait2() {
    asm volatile("cp.async.wait_group 2;" ::: "memory");
}

// -------- RoPE table -------------------------------------------------------
__global__ void rope_table_kernel() {
    int idx = blockIdx.x * blockDim.x + threadIdx.x;
    if (idx >= SEQ*HD) return;
    int s = idx >> 7;
    int d = idx & 127;
    int j = d >> 1;
    float inv = (float)exp(-2.0 * (double)j / 128.0 * log(10000.0));
    float ang = (float)s * inv;
    g_sin[idx] = (float)sin((double)ang);
    g_cos[idx] = (float)cos((double)ang);
}

// -------- elementwise tf32 convert ----------------------------------------
__global__ void cvt_tf32_kernel(const float* __restrict__ in, float* __restrict__ out) {
    int i = (blockIdx.x * blockDim.x + threadIdx.x) * 4;
    float4 v = *(const float4*)(in + i);
    uint4 o;
    o.x = f2tf(v.x); o.y = f2tf(v.y); o.z = f2tf(v.z); o.w = f2tf(v.w);
    *(uint4*)(out + i) = o;
}

// -------- TF32 mma.sync GEMM with cp.async 4-stage pipeline ----------------
// C = A[M,K] @ B[K,N] + bias. Inputs already tf32 bits.
// MODE 0: row-major store (fp32); MODE 1: [b][h][s][d] + RoPE (tf32 bits out);
// MODE 2: [b][h][s][d] (tf32 bits out).
// Tile 128x128, BK=16, 256 thr, 8 warps (2x4), warp tile 64x32 (m16n8k8).
#define AS_STRIDE 20      // words per m-row (16 k + 4 pad)
#define BS_STRIDE 136     // words per k-row (128 n + 8 pad)
#define STAGE_WORDS (128*AS_STRIDE + 16*BS_STRIDE)   // 4736
#define NSTAGE 4
#define GSMEM_BYTES (NSTAGE * STAGE_WORDS * 4)       // 75776

template<int MODE>
__global__ __launch_bounds__(256, 2) void gemm_ca(
    const float* __restrict__ A, const float* __restrict__ Bm,
    const float* __restrict__ bias, float* __restrict__ C,
    int N, int K)
{
    extern __shared__ unsigned smem[];
    const uint32_t sbase = smem_u32(smem);

    const int t    = threadIdx.x;
    const int wid  = t >> 5;
    const int lane = t & 31;
    const int g    = lane >> 2;
    const int c    = lane & 3;
    const int wrow = wid >> 2;    // 0..1
    const int wcol = wid & 3;     // 0..3
    const int m0 = blockIdx.y * 128;
    const int n0 = blockIdx.x * 128;

    // loader mapping: 2 A-chunks + 2 B-chunks per thread
    const float* aSrc[2]; uint32_t aOff[2];
    const float* bSrc[2]; uint32_t bOff[2];
    #pragma unroll
    for (int s = 0; s < 2; s++) {
        int idx = s * 256 + t;
        int r  = idx >> 2, kq = idx & 3;          // A: 128 rows x 4 quads
        aSrc[s] = A + (size_t)(m0 + r) * K + kq * 4;
        aOff[s] = (r * AS_STRIDE + kq * 4) * 4;
        int kr = idx >> 5, nc = (idx & 31) * 4;   // B: 16 rows x 32 quads
        bSrc[s] = Bm + (size_t)kr * N + n0 + nc;
        bOff[s] = (16384 /*128*20*4? no: AS region bytes*/ ) ; // placeholder
        bOff[s] = (128 * AS_STRIDE + kr * BS_STRIDE) * 4 + nc * 4;
    }

    float acc[4][4][4];
    #pragma unroll
    for (int i = 0; i < 4; i++)
        #pragma unroll
        for (int j = 0; j < 4; j++)
            #pragma unroll
            for (int r = 0; r < 4; r++) acc[i][j][r] = 0.0f;

    const int NIT = K >> 4;   // 128

    // prologue: stages 0..2
    #pragma unroll
    for (int p = 0; p < 3; p++) {
        uint32_t sb = sbase + p * (STAGE_WORDS * 4);
        #pragma unroll
        for (int s = 0; s < 2; s++) {
            cpa16(sb + aOff[s], aSrc[s] + p * 16);
            cpa16(sb + bOff[s], bSrc[s] + (size_t)p * 16 * N);
        }
        cpa_commit();
    }

    for (int i = 0; i < NIT; i++) {
        cpa_wait2();          // tile i resident (each thread's own copies)
        __syncthreads();      // visible to all; compute(i-1) done by all

        // issue tile i+3 into stage (i+3)&3 (buffer used by compute(i-1))
        {
            int nt = i + 3;
            uint32_t sb = sbase + (nt & 3) * (STAGE_WORDS * 4);
            if (nt < NIT) {
                #pragma unroll
                for (int s = 0; s < 2; s++) {
                    cpa16(sb + aOff[s], aSrc[s] + nt * 16);
                    cpa16(sb + bOff[s], bSrc[s] + (size_t)nt * 16 * N);
                }
            }
            cpa_commit();     // unconditional: keep group numbering uniform
        }

        // compute on stage i&3
        const uint32_t stw = (i & 3) * STAGE_WORDS;
        unsigned* As = smem + stw;
        unsigned* Bs = smem + stw + 128 * AS_STRIDE;
        #pragma unroll
        for (int ks = 0; ks < 2; ks++) {
            const int kb = ks * 8;
            unsigned a[4][4];
            #pragma unroll
            for (int mt = 0; mt < 4; mt++) {
                const int mb = wrow * 64 + mt * 16;
                a[mt][0] = As[(mb + g)     * AS_STRIDE + kb + c];
                a[mt][1] = As[(mb + g + 8) * AS_STRIDE + kb + c];
                a[mt][2] = As[(mb + g)     * AS_STRIDE + kb + c + 4];
                a[mt][3] = As[(mb + g + 8) * AS_STRIDE + kb + c + 4];
            }
            #pragma unroll
            for (int nt = 0; nt < 4; nt++) {
                const int nb = wcol * 32 + nt * 8 + g;
                unsigned b[2];
                b[0] = Bs[(kb + c)     * BS_STRIDE + nb];
                b[1] = Bs[(kb + c + 4) * BS_STRIDE + nb];
                #pragma unroll
                for (int mt = 0; mt < 4; mt++)
                    mma_tf32(acc[mt][nt], a[mt], b);
            }
        }
    }

    // Epilogue: fragment (mt,nt): rows mb+g, mb+g+8; cols nb+2c, nb+2c+1
    #pragma unroll
    for (int mt = 0; mt < 4; mt++) {
        #pragma unroll
        for (int nt = 0; nt < 4; nt++) {
            const int col = n0 + wcol * 32 + nt * 8 + 2 * c;
            #pragma unroll
            for (int half = 0; half < 2; half++) {
                const int row = m0 + wrow * 64 + mt * 16 + g + half * 8;
                float v0 = acc[mt][nt][half * 2 + 0] + bias[col];
                float v1 = acc[mt][nt][half * 2 + 1] + bias[col + 1];
                if (MODE == 0) {
                    float2 o = make_float2(v0, v1);
                    *(float2*)(C + (size_t)row * N + col) = o;
                } else {
                    const int b = row >> 11;
                    const int s = row & (SEQ - 1);
                    const int h = col >> 7;
                    const int d = col & 127;
                    if (MODE == 1) {
                        float sn = g_sin[s * HD + d];
                        float cs = g_cos[s * HD + d];
                        float o0 = v0 * cs - v1 * sn;
                        float o1 = v1 * cs + v0 * sn;
                        v0 = o0; v1 = o1;
                    }
                    size_t oidx = ((size_t)((b * NH + h) * SEQ + s)) * HD + d;
                    float2 o = make_float2(__uint_as_float(f2tf(v0)),
                                           __uint_as_float(f2tf(v1)));
                    *(float2*)(&C[oidx]) = o;
                }
            }
        }
    }
}

// -------- Flash attention, TF32 mma.sync (inputs tf32 bits) ----------------
#define QK_STRIDE 132
#define V_STRIDE  136
#define P_STRIDE  68

#define SM_QS 0
#define SM_KS (SM_QS + 128*QK_STRIDE)
#define SM_VS (SM_KS + 64*QK_STRIDE)
#define SM_PS (SM_VS + 64*V_STRIDE)
#define SM_M  (SM_PS + 128*P_STRIDE)
#define SM_L  (SM_M + 128)
#define SM_F  (SM_L + 128)
#define SM_TOT (SM_F + 128)
#define SMEM_ATTN_BYTES (SM_TOT * 4)

__global__ __launch_bounds__(512, 1) void attn_kernel() {
    extern __shared__ unsigned sm[];
    unsigned* Qs = sm + SM_QS;
    unsigned* Ks = sm + SM_KS;
    unsigned* Vs = sm + SM_VS;
    unsigned* Ps = sm + SM_PS;
    float* mrow = (float*)(sm + SM_M);
    float* lrow = (float*)(sm + SM_L);
    float* frow = (float*)(sm + SM_F);

    const int t    = threadIdx.x;
    const int wid  = t >> 5;
    const int lane = t & 31;
    const int g    = lane >> 2;
    const int c    = lane & 3;
    const int wrow = wid >> 2;
    const int wcol = wid & 3;

    const int q0 = blockIdx.x * 128;
    const int h  = blockIdx.y;
    const int b  = blockIdx.z;
    const size_t bh_off = (size_t)(b * NH + h) * SEQ * HD;
    const float* qg = g_q + bh_off;
    const float* kg = g_k + bh_off;
    const float* vg = g_v + bh_off;

    #pragma unroll
    for (int i = 0; i < 8; i++) {
        int lin = (i * 512 + t) * 4;
        int r = lin >> 7;
        int d = lin & 127;
        uint4 v = *(const uint4*)(qg + (size_t)(q0 + r) * HD + d);
        *(uint4*)&Qs[r * QK_STRIDE + d] = v;
    }
    if (t < 128) { mrow[t] = -INFINITY; lrow[t] = 0.0f; }

    float oacc[2][4][4];
    #pragma unroll
    for (int i = 0; i < 2; i++)
        #pragma unroll
        for (int j = 0; j < 4; j++)
            #pragma unroll
            for (int r = 0; r < 4; r++) oacc[i][j][r] = 0.0f;

    const float scale = 0.08838834764831845f;
    const int srow = t >> 2;
    const int sseg = t & 3;

    for (int kv0 = 0; kv0 < SEQ; kv0 += 64) {
        __syncthreads();
        #pragma unroll
        for (int i = 0; i < 4; i++) {
            int lin = (i * 512 + t) * 4;
            int r = lin >> 7;
            int d = lin & 127;
            uint4 kv = *(const uint4*)(kg + (size_t)(kv0 + r) * HD + d);
            *(uint4*)&Ks[r * QK_STRIDE + d] = kv;
            uint4 vv = *(const uint4*)(vg + (size_t)(kv0 + r) * HD + d);
            *(uint4*)&Vs[r * V_STRIDE + d] = vv;
        }
        __syncthreads();

        float sacc[2][2][4];
        #pragma unroll
        for (int i = 0; i < 2; i++)
            #pragma unroll
            for (int j = 0; j < 2; j++)
                #pragma unroll
                for (int r = 0; r < 4; r++) sacc[i][j][r] = 0.0f;

        #pragma unroll 4
        for (int ks = 0; ks < 16; ks++) {
            const int kb = ks * 8;
            unsigned a[2][4];
            #pragma unroll
            for (int mt = 0; mt < 2; mt++) {
                const int mb = wrow * 32 + mt * 16;
                a[mt][0] = Qs[(mb + g)     * QK_STRIDE + kb + c];
                a[mt][1] = Qs[(mb + g + 8) * QK_STRIDE + kb + c];
                a[mt][2] = Qs[(mb + g)     * QK_STRIDE + kb + c + 4];
                a[mt][3] = Qs[(mb + g + 8) * QK_STRIDE + kb + c + 4];
            }
            #pragma unroll
            for (int nt = 0; nt < 2; nt++) {
                const int nb = wcol * 16 + nt * 8 + g;
                unsigned bb[2];
                bb[0] = Ks[nb * QK_STRIDE + kb + c];
                bb[1] = Ks[nb * QK_STRIDE + kb + c + 4];
                #pragma unroll
                for (int mt = 0; mt < 2; mt++)
                    mma_tf32(sacc[mt][nt], a[mt], bb);
            }
        }

        #pragma unroll
        for (int mt = 0; mt < 2; mt++) {
            #pragma unroll
            for (int nt = 0; nt < 2; nt++) {
                const int col = wcol * 16 + nt * 8 + 2 * c;
                #pragma unroll
                for (int half = 0; half < 2; half++) {
                    const int row = wrow * 32 + mt * 16 + g + half * 8;
                    float2 o = make_float2(sacc[mt][nt][half*2+0] * scale,
                                           sacc[mt][nt][half*2+1] * scale);
                    *(float2*)(&Ps[row * P_STRIDE + col]) = o;
                }
            }
        }
        __syncthreads();

        {
            float* prow = (float*)&Ps[srow * P_STRIDE + sseg * 16];
            float mold = mrow[srow];
            float mx = -INFINITY;
            #pragma unroll
            for (int i = 0; i < 16; i++) mx = fmaxf(mx, prow[i]);
            mx = fmaxf(mx, __shfl_xor_sync(0xffffffffu, mx, 1));
            mx = fmaxf(mx, __shfl_xor_sync(0xffffffffu, mx, 2));
            float mnew = fmaxf(mold, mx);
            float fac = __expf(mold - mnew);
            float psum = 0.0f;
            #pragma unroll
            for (int i = 0; i < 16; i++) {
                float p = __expf(prow[i] - mnew);
                p = __uint_as_float(f2tf(p));
                prow[i] = p;
                psum += p;
            }
            psum += __shfl_xor_sync(0xffffffffu, psum, 1);
            psum += __shfl_xor_sync(0xffffffffu, psum, 2);
            if (sseg == 0) {
                lrow[srow] = lrow[srow] * fac + psum;
                mrow[srow] = mnew;
                frow[srow] = fac;
            }
        }
        __syncthreads();

        #pragma unroll
        for (int mt = 0; mt < 2; mt++) {
            const int mb = wrow * 32 + mt * 16;
            const float f1 = frow[mb + g];
            const float f2 = frow[mb + g + 8];
            #pragma unroll
            for (int nt = 0; nt < 4; nt++) {
                oacc[mt][nt][0] *= f1; oacc[mt][nt][1] *= f1;
                oacc[mt][nt][2] *= f2; oacc[mt][nt][3] *= f2;
            }
        }
        #pragma unroll 2
        for (int ks = 0; ks < 8; ks++) {
            const int kb = ks * 8;
            unsigned a[2][4];
            #pragma unroll
            for (int mt = 0; mt < 2; mt++) {
                const int mb = wrow * 32 + mt * 16;
                a[mt][0] = Ps[(mb + g)     * P_STRIDE + kb + c];
                a[mt][1] = Ps[(mb + g + 8) * P_STRIDE + kb + c];
                a[mt][2] = Ps[(mb + g)     * P_STRIDE + kb + c + 4];
                a[mt][3] = Ps[(mb + g + 8) * P_STRIDE + kb + c + 4];
            }
            #pragma unroll
            for (int nt = 0; nt < 4; nt++) {
                const int nb = wcol * 32 + nt * 8 + g;
                unsigned bb[2];
                bb[0] = Vs[(kb + c)     * V_STRIDE + nb];
                bb[1] = Vs[(kb + c + 4) * V_STRIDE + nb];
                #pragma unroll
                for (int mt = 0; mt < 2; mt++)
                    mma_tf32(oacc[mt][nt], a[mt], bb);
            }
        }
    }
    __syncthreads();

    #pragma unroll
    for (int mt = 0; mt < 2; mt++) {
        #pragma unroll
        for (int half = 0; half < 2; half++) {
            const int row = wrow * 32 + mt * 16 + g + half * 8;
            const float invl = 1.0f / lrow[row];
            #pragma unroll
            for (int nt = 0; nt < 4; nt++) {
                const int col = wcol * 32 + nt * 8 + 2 * c;
                size_t base = ((size_t)(b * SEQ + q0 + row)) * HID + h * HD + col;
                float2 o;
                o.x = __uint_as_float(f2tf(oacc[mt][nt][half*2+0] * invl));
                o.y = __uint_as_float(f2tf(oacc[mt][nt][half*2+1] * invl));
                *(float2*)(g_att + base) = o;
            }
        }
    }
}

// ---------------------------------------------------------------------------
extern "C" void kernel_launch(void* const* d_in, const int* in_sizes, int n_in,
                              void* d_out, int out_size) {
    const float* X  = (const float*)d_in[0];
    const float* Wq = (const float*)d_in[1];
    const float* bq = (const float*)d_in[2];
    const float* Wk = (const float*)d_in[3];
    const float* bk = (const float*)d_in[4];
    const float* Wv = (const float*)d_in[5];
    const float* bv = (const float*)d_in[6];
    const float* Wo = (const float*)d_in[7];
    const float* bo = (const float*)d_in[8];
    float* out = (float*)d_out;

    float *q, *k, *v, *att, *xtf, *wq, *wk, *wv, *wo;
    cudaGetSymbolAddress((void**)&q,   g_q);
    cudaGetSymbolAddress((void**)&k,   g_k);
    cudaGetSymbolAddress((void**)&v,   g_v);
    cudaGetSymbolAddress((void**)&att, g_att);
    cudaGetSymbolAddress((void**)&xtf, g_xtf);
    cudaGetSymbolAddress((void**)&wq,  g_wq);
    cudaGetSymbolAddress((void**)&wk,  g_wk);
    cudaGetSymbolAddress((void**)&wv,  g_wv);
    cudaGetSymbolAddress((void**)&wo,  g_wo);

    cudaFuncSetAttribute(attn_kernel,
                         cudaFuncAttributeMaxDynamicSharedMemorySize, SMEM_ATTN_BYTES);
    cudaFuncSetAttribute(gemm_ca<0>,
                         cudaFuncAttributeMaxDynamicSharedMemorySize, GSMEM_BYTES);
    cudaFuncSetAttribute(gemm_ca<1>,
                         cudaFuncAttributeMaxDynamicSharedMemorySize, GSMEM_BYTES);
    cudaFuncSetAttribute(gemm_ca<2>,
                         cudaFuncAttributeMaxDynamicSharedMemorySize, GSMEM_BYTES);

    rope_table_kernel<<<(SEQ * HD + 255) / 256, 256>>>();

    const int cvt_grid = (MROWS * HID / 4) / 256;
    cvt_tf32_kernel<<<cvt_grid, 256>>>(X, xtf);
    const int wcvt_grid = (HID * HID / 4) / 256;
    cvt_tf32_kernel<<<wcvt_grid, 256>>>(Wq, wq);
    cvt_tf32_kernel<<<wcvt_grid, 256>>>(Wk, wk);
    cvt_tf32_kernel<<<wcvt_grid, 256>>>(Wv, wv);
    cvt_tf32_kernel<<<wcvt_grid, 256>>>(Wo, wo);

    dim3 gg(HID / 128, MROWS / 128);
    gemm_ca<1><<<gg, 256, GSMEM_BYTES>>>(xtf, wq, bq, q, HID, HID);
    gemm_ca<1><<<gg, 256, GSMEM_BYTES>>>(xtf, wk, bk, k, HID, HID);
    gemm_ca<2><<<gg, 256, GSMEM_BYTES>>>(xtf, wv, bv, v, HID, HID);

    attn_kernel<<<dim3(SEQ / 128, NH, BATCH), 512, SMEM_ATTN_BYTES>>>();

    gemm_ca<0><<<gg, 256, GSMEM_BYTES>>>(att, wo, bo, out, HID, HID);
}

// round 6
// speedup vs baseline: 3.5905x; 1.0195x over previous
#include <cuda_runtime.h>
#include <math.h>
#include <stdint.h>

#define BATCH 2
#define SEQ   2048
#define HID   2048
#define NH    16
#define HD    128
#define MROWS (BATCH*SEQ)   // 4096

// -------- scratch (static device globals) ---------------------------------
__device__ float g_q[BATCH*NH*SEQ*HD];     // tf32 bits, rope applied
__device__ float g_k[BATCH*NH*SEQ*HD];
__device__ float g_v[BATCH*NH*SEQ*HD];
__device__ float g_att[MROWS*HID];         // tf32 bits
__device__ float g_xtf[MROWS*HID];         // X tf32 bits
__device__ float g_wq[HID*HID];            // W tf32 bits [K,N]
__device__ float g_wk[HID*HID];
__device__ float g_wv[HID*HID];
__device__ float g_wo[HID*HID];
__device__ float g_sin[SEQ*HD];
__device__ float g_cos[SEQ*HD];

// -------- helpers ----------------------------------------------------------
__device__ __forceinline__ unsigned f2tf(float x) {
    unsigned r;
    asm("cvt.rna.tf32.f32 %0, %1;" : "=r"(r) : "f"(x));
    return r;
}

__device__ __forceinline__ void mma_tf32(float* d, const unsigned* a, const unsigned* b) {
    asm volatile(
        "mma.sync.aligned.m16n8k8.row.col.f32.tf32.tf32.f32 "
        "{%0,%1,%2,%3}, {%4,%5,%6,%7}, {%8,%9}, {%0,%1,%2,%3};"
        : "+f"(d[0]), "+f"(d[1]), "+f"(d[2]), "+f"(d[3])
        : "r"(a[0]), "r"(a[1]), "r"(a[2]), "r"(a[3]), "r"(b[0]), "r"(b[1]));
}

__device__ __forceinline__ uint32_t smem_u32(const void* p) {
    uint32_t a;
    asm("{ .reg .u64 t; cvta.to.shared.u64 t, %1; cvt.u32.u64 %0, t; }"
        : "=r"(a) : "l"(p));
    return a;
}

__device__ __forceinline__ void cpa16(uint32_t dst, const float* src) {
    asm volatile(
        "{ .reg .u64 ga; cvta.to.global.u64 ga, %1;"
        "  cp.async.cg.shared.global [%0], [ga], 16; }"
        :: "r"(dst), "l"(src) : "memory");
}
__device__ __forceinline__ void cpa_commit() {
    asm volatile("cp.async.commit_group;" ::: "memory");
}
__device__ __forceinline__ void cpa_wait0() {
    asm volatile("cp.async.wait_group 0;" ::: "memory");
}
__device__ __forceinline__ void cpa_wait1() {
    asm volatile("cp.async.wait_group 1;" ::: "memory");
}
__device__ __forceinline__ void cpa_wait2() {
    asm volatile("cp.async.wait_group 2;" ::: "memory");
}

// -------- RoPE table -------------------------------------------------------
__global__ void rope_table_kernel() {
    int idx = blockIdx.x * blockDim.x + threadIdx.x;
    if (idx >= SEQ*HD) return;
    int s = idx >> 7;
    int d = idx & 127;
    int j = d >> 1;
    float inv = (float)exp(-2.0 * (double)j / 128.0 * log(10000.0));
    float ang = (float)s * inv;
    g_sin[idx] = (float)sin((double)ang);
    g_cos[idx] = (float)cos((double)ang);
}

// -------- elementwise tf32 convert ----------------------------------------
__global__ void cvt_tf32_kernel(const float* __restrict__ in, float* __restrict__ out) {
    int i = (blockIdx.x * blockDim.x + threadIdx.x) * 4;
    float4 v = *(const float4*)(in + i);
    uint4 o;
    o.x = f2tf(v.x); o.y = f2tf(v.y); o.z = f2tf(v.z); o.w = f2tf(v.w);
    *(uint4*)(out + i) = o;
}

// -------- TF32 mma.sync GEMM body with cp.async 4-stage pipeline -----------
// C = A[M,K] @ B[K,N] + bias (all tf32 bits in).
// mode 0: row-major fp32 store; mode 1: [b][h][s][d] + RoPE (tf32 out);
// mode 2: [b][h][s][d] (tf32 out).
#define AS_STRIDE 20
#define BS_STRIDE 136
#define STAGE_WORDS (128*AS_STRIDE + 16*BS_STRIDE)   // 4736
#define GSMEM_BYTES (4 * STAGE_WORDS * 4)            // 75776

__device__ __forceinline__ void gemm_body(
    const int mode,
    const float* __restrict__ A, const float* __restrict__ Bm,
    const float* __restrict__ bias, float* __restrict__ C,
    unsigned* smem, const int N, const int K)
{
    const uint32_t sbase = smem_u32(smem);

    const int t    = threadIdx.x;
    const int wid  = t >> 5;
    const int lane = t & 31;
    const int g    = lane >> 2;
    const int c    = lane & 3;
    const int wrow = wid >> 2;
    const int wcol = wid & 3;
    const int m0 = blockIdx.y * 128;
    const int n0 = blockIdx.x * 128;

    const float* aSrc[2]; uint32_t aOff[2];
    const float* bSrc[2]; uint32_t bOff[2];
    #pragma unroll
    for (int s = 0; s < 2; s++) {
        int idx = s * 256 + t;
        int r  = idx >> 2, kq = idx & 3;
        aSrc[s] = A + (size_t)(m0 + r) * K + kq * 4;
        aOff[s] = (r * AS_STRIDE + kq * 4) * 4;
        int kr = idx >> 5, nc = (idx & 31) * 4;
        bSrc[s] = Bm + (size_t)kr * N + n0 + nc;
        bOff[s] = (128 * AS_STRIDE + kr * BS_STRIDE + nc) * 4;
    }

    float acc[4][4][4];
    #pragma unroll
    for (int i = 0; i < 4; i++)
        #pragma unroll
        for (int j = 0; j < 4; j++)
            #pragma unroll
            for (int r = 0; r < 4; r++) acc[i][j][r] = 0.0f;

    const int NIT = K >> 4;

    #pragma unroll
    for (int p = 0; p < 3; p++) {
        uint32_t sb = sbase + p * (STAGE_WORDS * 4);
        #pragma unroll
        for (int s = 0; s < 2; s++) {
            cpa16(sb + aOff[s], aSrc[s] + p * 16);
            cpa16(sb + bOff[s], bSrc[s] + (size_t)p * 16 * N);
        }
        cpa_commit();
    }

    for (int i = 0; i < NIT; i++) {
        cpa_wait2();
        __syncthreads();

        {
            int nt = i + 3;
            uint32_t sb = sbase + (nt & 3) * (STAGE_WORDS * 4);
            if (nt < NIT) {
                #pragma unroll
                for (int s = 0; s < 2; s++) {
                    cpa16(sb + aOff[s], aSrc[s] + nt * 16);
                    cpa16(sb + bOff[s], bSrc[s] + (size_t)nt * 16 * N);
                }
            }
            cpa_commit();
        }

        const uint32_t stw = (i & 3) * STAGE_WORDS;
        unsigned* As = smem + stw;
        unsigned* Bs = smem + stw + 128 * AS_STRIDE;
        #pragma unroll
        for (int ks = 0; ks < 2; ks++) {
            const int kb = ks * 8;
            unsigned a[4][4];
            #pragma unroll
            for (int mt = 0; mt < 4; mt++) {
                const int mb = wrow * 64 + mt * 16;
                a[mt][0] = As[(mb + g)     * AS_STRIDE + kb + c];
                a[mt][1] = As[(mb + g + 8) * AS_STRIDE + kb + c];
                a[mt][2] = As[(mb + g)     * AS_STRIDE + kb + c + 4];
                a[mt][3] = As[(mb + g + 8) * AS_STRIDE + kb + c + 4];
            }
            #pragma unroll
            for (int nt = 0; nt < 4; nt++) {
                const int nb = wcol * 32 + nt * 8 + g;
                unsigned b[2];
                b[0] = Bs[(kb + c)     * BS_STRIDE + nb];
                b[1] = Bs[(kb + c + 4) * BS_STRIDE + nb];
                #pragma unroll
                for (int mt = 0; mt < 4; mt++)
                    mma_tf32(acc[mt][nt], a[mt], b);
            }
        }
    }

    #pragma unroll
    for (int mt = 0; mt < 4; mt++) {
        #pragma unroll
        for (int nt = 0; nt < 4; nt++) {
            const int col = n0 + wcol * 32 + nt * 8 + 2 * c;
            #pragma unroll
            for (int half = 0; half < 2; half++) {
                const int row = m0 + wrow * 64 + mt * 16 + g + half * 8;
                float v0 = acc[mt][nt][half * 2 + 0] + bias[col];
                float v1 = acc[mt][nt][half * 2 + 1] + bias[col + 1];
                if (mode == 0) {
                    float2 o = make_float2(v0, v1);
                    *(float2*)(C + (size_t)row * N + col) = o;
                } else {
                    const int b = row >> 11;
                    const int s = row & (SEQ - 1);
                    const int h = col >> 7;
                    const int d = col & 127;
                    if (mode == 1) {
                        float sn = g_sin[s * HD + d];
                        float cs = g_cos[s * HD + d];
                        float o0 = v0 * cs - v1 * sn;
                        float o1 = v1 * cs + v0 * sn;
                        v0 = o0; v1 = o1;
                    }
                    size_t oidx = ((size_t)((b * NH + h) * SEQ + s)) * HD + d;
                    float2 o = make_float2(__uint_as_float(f2tf(v0)),
                                           __uint_as_float(f2tf(v1)));
                    *(float2*)(&C[oidx]) = o;
                }
            }
        }
    }
}

// fused Q/K/V projection: blockIdx.z selects weight/bias/output/mode
__global__ __launch_bounds__(256, 2) void qkv_gemm(
    const float* __restrict__ bq, const float* __restrict__ bk,
    const float* __restrict__ bv)
{
    extern __shared__ unsigned smem[];
    const float* Bm; const float* bias; float* C; int mode;
    if (blockIdx.z == 0)      { Bm = g_wq; bias = bq; C = g_q; mode = 1; }
    else if (blockIdx.z == 1) { Bm = g_wk; bias = bk; C = g_k; mode = 1; }
    else                      { Bm = g_wv; bias = bv; C = g_v; mode = 2; }
    gemm_body(mode, g_xtf, Bm, bias, C, smem, HID, HID);
}

__global__ __launch_bounds__(256, 2) void gemm_o(
    const float* __restrict__ A, const float* __restrict__ Bm,
    const float* __restrict__ bias, float* __restrict__ C)
{
    extern __shared__ unsigned smem[];
    gemm_body(0, A, Bm, bias, C, smem, HID, HID);
}

// -------- Flash attention: cp.async + XOR-swizzled smem --------------------
// Br=128, Bc=64, 512 threads. Q resident; K double-buffered; V 1-ahead.
// Word-index layout (stride 128 for Q/K/V rows, 64 for P rows):
//   Q/K/P swizzle: word ^= (row&7)<<2 ; V swizzle: word ^= (row&3)<<3
#define ATT_Q 0
#define ATT_K (ATT_Q + 128*128)          // 16384
#define ATT_V (ATT_K + 2*64*128)         // 32768
#define ATT_P (ATT_V + 64*128)           // 40960
#define ATT_M (ATT_P + 128*64)           // 49152
#define ATT_L (ATT_M + 128)
#define ATT_F (ATT_L + 128)
#define ATT_TOT (ATT_F + 128)            // 49536 words
#define SMEM_ATTN_BYTES (ATT_TOT * 4)    // 198144

__global__ __launch_bounds__(512, 1) void attn_kernel() {
    extern __shared__ unsigned sm[];
    const uint32_t sbase = smem_u32(sm);
    unsigned* Qs = sm + ATT_Q;
    unsigned* Ks = sm + ATT_K;
    unsigned* Vs = sm + ATT_V;
    unsigned* Ps = sm + ATT_P;
    float* mrow = (float*)(sm + ATT_M);
    float* lrow = (float*)(sm + ATT_L);
    float* frow = (float*)(sm + ATT_F);

    const int t    = threadIdx.x;
    const int wid  = t >> 5;
    const int lane = t & 31;
    const int g    = lane >> 2;
    const int c    = lane & 3;
    const int gx   = g << 2;          // QK/P swizzle for fragment rows
    const int cx   = c << 3;          // V swizzle for fragment rows kb+c
    const int wrow = wid >> 2;
    const int wcol = wid & 3;

    const int q0 = blockIdx.x * 128;
    const int h  = blockIdx.y;
    const int b  = blockIdx.z;
    const size_t bh_off = (size_t)(b * NH + h) * SEQ * HD;
    const float* qg = g_q + bh_off;
    const float* kg = g_k + bh_off;
    const float* vg = g_v + bh_off;

    // ---- prologue: async Q + K(0) + V(0) (G0), K(1) (G1) ----
    #pragma unroll
    for (int p = 0; p < 8; p++) {
        int lin = (p * 512 + t) * 4;
        int r = lin >> 7, w = lin & 127;
        cpa16(sbase + (ATT_Q + r * 128 + (w ^ ((r & 7) << 2))) * 4,
              qg + (size_t)(q0 + r) * HD + w);
    }
    #pragma unroll
    for (int p = 0; p < 4; p++) {
        int lin = (p * 512 + t) * 4;
        int r = lin >> 7, w = lin & 127;
        cpa16(sbase + (ATT_K + r * 128 + (w ^ ((r & 7) << 2))) * 4,
              kg + (size_t)r * HD + w);
        cpa16(sbase + (ATT_V + r * 128 + (w ^ ((r & 3) << 3))) * 4,
              vg + (size_t)r * HD + w);
    }
    cpa_commit();
    #pragma unroll
    for (int p = 0; p < 4; p++) {
        int lin = (p * 512 + t) * 4;
        int r = lin >> 7, w = lin & 127;
        cpa16(sbase + (ATT_K + 64*128 + r * 128 + (w ^ ((r & 7) << 2))) * 4,
              kg + (size_t)(64 + r) * HD + w);
    }
    cpa_commit();

    if (t < 128) { mrow[t] = -INFINITY; lrow[t] = 0.0f; }

    float oacc[2][4][4];
    #pragma unroll
    for (int i = 0; i < 2; i++)
        #pragma unroll
        for (int j = 0; j < 4; j++)
            #pragma unroll
            for (int r = 0; r < 4; r++) oacc[i][j][r] = 0.0f;

    const float scale = 0.08838834764831845f;
    const int srow = t >> 2;
    const int sseg = t & 3;
    const int sx   = (srow & 7) << 2;

    cpa_wait1();          // G0 done: Q, K0, V0
    __syncthreads();

    for (int it = 0; it < SEQ / 64; it++) {
        const unsigned* Kb = Ks + (it & 1) * 64 * 128;

        // ---- S = Q @ K^T ----
        float sacc[2][2][4];
        #pragma unroll
        for (int i = 0; i < 2; i++)
            #pragma unroll
            for (int j = 0; j < 2; j++)
                #pragma unroll
                for (int r = 0; r < 4; r++) sacc[i][j][r] = 0.0f;

        #pragma unroll 4
        for (int ks = 0; ks < 16; ks++) {
            const int kb = ks * 8;
            const int k0s = (kb ^ gx) | c;
            const int k1s = ((kb + 4) ^ gx) | c;
            unsigned a[2][4];
            #pragma unroll
            for (int mt = 0; mt < 2; mt++) {
                const int mb = wrow * 32 + mt * 16;
                a[mt][0] = Qs[(mb + g)     * 128 + k0s];
                a[mt][1] = Qs[(mb + g + 8) * 128 + k0s];
                a[mt][2] = Qs[(mb + g)     * 128 + k1s];
                a[mt][3] = Qs[(mb + g + 8) * 128 + k1s];
            }
            #pragma unroll
            for (int nt = 0; nt < 2; nt++) {
                const int nb = wcol * 16 + nt * 8 + g;
                unsigned bb[2];
                bb[0] = Kb[nb * 128 + k0s];
                bb[1] = Kb[nb * 128 + k1s];
                #pragma unroll
                for (int mt = 0; mt < 2; mt++)
                    mma_tf32(sacc[mt][nt], a[mt], bb);
            }
        }

        // ---- store scaled logits to Ps (swizzled) ----
        #pragma unroll
        for (int mt = 0; mt < 2; mt++) {
            #pragma unroll
            for (int nt = 0; nt < 2; nt++) {
                const int col = (wcol * 16 + nt * 8 + 2 * c) ^ gx;
                #pragma unroll
                for (int half = 0; half < 2; half++) {
                    const int row = wrow * 32 + mt * 16 + g + half * 8;
                    float2 o = make_float2(sacc[mt][nt][half*2+0] * scale,
                                           sacc[mt][nt][half*2+1] * scale);
                    *(float2*)(&Ps[row * 64 + col]) = o;
                }
            }
        }
        __syncthreads();

        // ---- online softmax (swizzled row reads; order-independent) ----
        {
            float* Pf = (float*)Ps;
            float mold = mrow[srow];
            float vals[16];
            float mx = -INFINITY;
            #pragma unroll
            for (int i = 0; i < 16; i++) {
                vals[i] = Pf[srow * 64 + ((sseg * 16 + i) ^ sx)];
                mx = fmaxf(mx, vals[i]);
            }
            mx = fmaxf(mx, __shfl_xor_sync(0xffffffffu, mx, 1));
            mx = fmaxf(mx, __shfl_xor_sync(0xffffffffu, mx, 2));
            float mnew = fmaxf(mold, mx);
            float fac = __expf(mold - mnew);
            float psum = 0.0f;
            #pragma unroll
            for (int i = 0; i < 16; i++) {
                float p = __expf(vals[i] - mnew);
                p = __uint_as_float(f2tf(p));
                Pf[srow * 64 + ((sseg * 16 + i) ^ sx)] = p;
                psum += p;
            }
            psum += __shfl_xor_sync(0xffffffffu, psum, 1);
            psum += __shfl_xor_sync(0xffffffffu, psum, 2);
            if (sseg == 0) {
                lrow[srow] = lrow[srow] * fac + psum;
                mrow[srow] = mnew;
                frow[srow] = fac;
            }
        }
        cpa_wait0();      // V(it) (and in-flight K) complete
        __syncthreads();

        // ---- O = O*fac + P @ V ----
        #pragma unroll
        for (int mt = 0; mt < 2; mt++) {
            const int mb = wrow * 32 + mt * 16;
            const float f1 = frow[mb + g];
            const float f2 = frow[mb + g + 8];
            #pragma unroll
            for (int nt = 0; nt < 4; nt++) {
                oacc[mt][nt][0] *= f1; oacc[mt][nt][1] *= f1;
                oacc[mt][nt][2] *= f2; oacc[mt][nt][3] *= f2;
            }
        }
        #pragma unroll 2
        for (int ks = 0; ks < 8; ks++) {
            const int kb = ks * 8;
            const int k0s = (kb ^ gx) | c;
            const int k1s = ((kb + 4) ^ gx) | c;
            unsigned a[2][4];
            #pragma unroll
            for (int mt = 0; mt < 2; mt++) {
                const int mb = wrow * 32 + mt * 16;
                a[mt][0] = Ps[(mb + g)     * 64 + k0s];
                a[mt][1] = Ps[(mb + g + 8) * 64 + k0s];
                a[mt][2] = Ps[(mb + g)     * 64 + k1s];
                a[mt][3] = Ps[(mb + g + 8) * 64 + k1s];
            }
            #pragma unroll
            for (int nt = 0; nt < 4; nt++) {
                const int nbv = (wcol * 32 + nt * 8 + g) ^ cx;
                unsigned bb[2];
                bb[0] = Vs[(kb + c)     * 128 + nbv];
                bb[1] = Vs[(kb + c + 4) * 128 + nbv];
                #pragma unroll
                for (int mt = 0; mt < 2; mt++)
                    mma_tf32(oacc[mt][nt], a[mt], bb);
            }
        }
        __syncthreads();

        // ---- issue next tiles: V(it+1), K(it+2) ----
        if (it + 1 < SEQ / 64) {
            const int vnext = (it + 1) * 64;
            #pragma unroll
            for (int p = 0; p < 4; p++) {
                int lin = (p * 512 + t) * 4;
                int r = lin >> 7, w = lin & 127;
                cpa16(sbase + (ATT_V + r * 128 + (w ^ ((r & 3) << 3))) * 4,
                      vg + (size_t)(vnext + r) * HD + w);
            }
            if (it + 2 < SEQ / 64) {
                const int knext = (it + 2) * 64;
                const int kbuf = ATT_K + (it & 1) * 64 * 128;
                #pragma unroll
                for (int p = 0; p < 4; p++) {
                    int lin = (p * 512 + t) * 4;
                    int r = lin >> 7, w = lin & 127;
                    cpa16(sbase + (kbuf + r * 128 + (w ^ ((r & 7) << 2))) * 4,
                          kg + (size_t)(knext + r) * HD + w);
                }
            }
            cpa_commit();
        }
    }

    // ---- normalize + store to (B,S,H) row-major ----
    #pragma unroll
    for (int mt = 0; mt < 2; mt++) {
        #pragma unroll
        for (int half = 0; half < 2; half++) {
            const int row = wrow * 32 + mt * 16 + g + half * 8;
            const float invl = 1.0f / lrow[row];
            #pragma unroll
            for (int nt = 0; nt < 4; nt++) {
                const int col = wcol * 32 + nt * 8 + 2 * c;
                size_t base = ((size_t)(b * SEQ + q0 + row)) * HID + h * HD + col;
                float2 o;
                o.x = __uint_as_float(f2tf(oacc[mt][nt][half*2+0] * invl));
                o.y = __uint_as_float(f2tf(oacc[mt][nt][half*2+1] * invl));
                *(float2*)(g_att + base) = o;
            }
        }
    }
}

// ---------------------------------------------------------------------------
extern "C" void kernel_launch(void* const* d_in, const int* in_sizes, int n_in,
                              void* d_out, int out_size) {
    const float* X  = (const float*)d_in[0];
    const float* Wq = (const float*)d_in[1];
    const float* bq = (const float*)d_in[2];
    const float* Wk = (const float*)d_in[3];
    const float* bk = (const float*)d_in[4];
    const float* Wv = (const float*)d_in[5];
    const float* bv = (const float*)d_in[6];
    const float* Wo = (const float*)d_in[7];
    const float* bo = (const float*)d_in[8];
    float* out = (float*)d_out;

    float *att, *xtf, *wq, *wk, *wv, *wo;
    cudaGetSymbolAddress((void**)&att, g_att);
    cudaGetSymbolAddress((void**)&xtf, g_xtf);
    cudaGetSymbolAddress((void**)&wq,  g_wq);
    cudaGetSymbolAddress((void**)&wk,  g_wk);
    cudaGetSymbolAddress((void**)&wv,  g_wv);
    cudaGetSymbolAddress((void**)&wo,  g_wo);

    cudaFuncSetAttribute(attn_kernel,
                         cudaFuncAttributeMaxDynamicSharedMemorySize, SMEM_ATTN_BYTES);
    cudaFuncSetAttribute(qkv_gemm,
                         cudaFuncAttributeMaxDynamicSharedMemorySize, GSMEM_BYTES);
    cudaFuncSetAttribute(gemm_o,
                         cudaFuncAttributeMaxDynamicSharedMemorySize, GSMEM_BYTES);

    rope_table_kernel<<<(SEQ * HD + 255) / 256, 256>>>();

    const int cvt_grid = (MROWS * HID / 4) / 256;
    cvt_tf32_kernel<<<cvt_grid, 256>>>(X, xtf);
    const int wcvt_grid = (HID * HID / 4) / 256;
    cvt_tf32_kernel<<<wcvt_grid, 256>>>(Wq, wq);
    cvt_tf32_kernel<<<wcvt_grid, 256>>>(Wk, wk);
    cvt_tf32_kernel<<<wcvt_grid, 256>>>(Wv, wv);
    cvt_tf32_kernel<<<wcvt_grid, 256>>>(Wo, wo);

    dim3 gg(HID / 128, MROWS / 128, 3);
    qkv_gemm<<<gg, 256, GSMEM_BYTES>>>(bq, bk, bv);

    attn_kernel<<<dim3(SEQ / 128, NH, BATCH), 512, SMEM_ATTN_BYTES>>>();

    dim3 go(HID / 128, MROWS / 128);
    gemm_o<<<go, 256, GSMEM_BYTES>>>(att, wo, bo, out);
}

// round 9
// speedup vs baseline: 3.7261x; 1.0378x over previous
#include <cuda_runtime.h>
#include <math.h>
#include <stdint.h>

#define BATCH 2
#define SEQ   2048
#define HID   2048
#define NH    16
#define HD    128
#define MROWS (BATCH*SEQ)   // 4096

// -------- scratch (static device globals) ---------------------------------
__device__ float g_q[BATCH*NH*SEQ*HD];     // tf32 bits, rope applied
__device__ float g_k[BATCH*NH*SEQ*HD];
__device__ float g_v[BATCH*NH*SEQ*HD];
__device__ float g_att[MROWS*HID];         // tf32 bits
__device__ float g_xtf[MROWS*HID];         // X tf32 bits
__device__ float g_wq[HID*HID];            // W tf32 bits [K,N]
__device__ float g_wk[HID*HID];
__device__ float g_wv[HID*HID];
__device__ float g_wo[HID*HID];
__device__ float g_sin[SEQ*HD];
__device__ float g_cos[SEQ*HD];

// -------- helpers ----------------------------------------------------------
__device__ __forceinline__ unsigned f2tf(float x) {
    unsigned r;
    asm("cvt.rna.tf32.f32 %0, %1;" : "=r"(r) : "f"(x));
    return r;
}

__device__ __forceinline__ void mma_tf32(float* d, const unsigned* a, const unsigned* b) {
    asm volatile(
        "mma.sync.aligned.m16n8k8.row.col.f32.tf32.tf32.f32 "
        "{%0,%1,%2,%3}, {%4,%5,%6,%7}, {%8,%9}, {%0,%1,%2,%3};"
        : "+f"(d[0]), "+f"(d[1]), "+f"(d[2]), "+f"(d[3])
        : "r"(a[0]), "r"(a[1]), "r"(a[2]), "r"(a[3]), "r"(b[0]), "r"(b[1]));
}

__device__ __forceinline__ uint32_t smem_u32(const void* p) {
    uint32_t a;
    asm("{ .reg .u64 t; cvta.to.shared.u64 t, %1; cvt.u32.u64 %0, t; }"
        : "=r"(a) : "l"(p));
    return a;
}

__device__ __forceinline__ void cpa16(uint32_t dst, const float* src) {
    asm volatile(
        "{ .reg .u64 ga; cvta.to.global.u64 ga, %1;"
        "  cp.async.cg.shared.global [%0], [ga], 16; }"
        :: "r"(dst), "l"(src) : "memory");
}
__device__ __forceinline__ void cpa_commit() {
    asm volatile("cp.async.commit_group;" ::: "memory");
}
__device__ __forceinline__ void cpa_wait0() {
    asm volatile("cp.async.wait_group 0;" ::: "memory");
}
__device__ __forceinline__ void cpa_wait2() {
    asm volatile("cp.async.wait_group 2;" ::: "memory");
}

// -------- RoPE table -------------------------------------------------------
__global__ void rope_table_kernel() {
    int idx = blockIdx.x * blockDim.x + threadIdx.x;
    if (idx >= SEQ*HD) return;
    int s = idx >> 7;
    int d = idx & 127;
    int j = d >> 1;
    float inv = (float)exp(-2.0 * (double)j / 128.0 * log(10000.0));
    float ang = (float)s * inv;
    g_sin[idx] = (float)sin((double)ang);
    g_cos[idx] = (float)cos((double)ang);
}

// -------- fused tf32 convert: X + 4 weights in one launch ------------------
// blocks [0,8192): X (MROWS*HID); then 4 x 4096 blocks for Wq/Wk/Wv/Wo.
__global__ void cvt_all_kernel(const float* __restrict__ X,
                               const float* __restrict__ Wq,
                               const float* __restrict__ Wk,
                               const float* __restrict__ Wv,
                               const float* __restrict__ Wo) {
    int b = blockIdx.x;
    const float* src; float* dst; int off;
    if (b < 8192) { src = X; dst = g_xtf; off = b; }
    else {
        int r = (b - 8192) >> 12;
        off = (b - 8192) & 4095;
        if (r == 0)      { src = Wq; dst = g_wq; }
        else if (r == 1) { src = Wk; dst = g_wk; }
        else if (r == 2) { src = Wv; dst = g_wv; }
        else             { src = Wo; dst = g_wo; }
    }
    int i = (off * 256 + threadIdx.x) * 4;
    float4 v = *(const float4*)(src + i);
    uint4 o;
    o.x = f2tf(v.x); o.y = f2tf(v.y); o.z = f2tf(v.z); o.w = f2tf(v.w);
    *(uint4*)(dst + i) = o;
}

// -------- TF32 mma.sync GEMM body with cp.async 4-stage pipeline -----------
#define AS_STRIDE 20
#define BS_STRIDE 136
#define STAGE_WORDS (128*AS_STRIDE + 16*BS_STRIDE)   // 4736
#define GSMEM_BYTES (4 * STAGE_WORDS * 4)            // 75776

__device__ __forceinline__ void gemm_body(
    const int mode,
    const float* __restrict__ A, const float* __restrict__ Bm,
    const float* __restrict__ bias, float* __restrict__ C,
    unsigned* smem, const int N, const int K)
{
    const uint32_t sbase = smem_u32(smem);

    const int t    = threadIdx.x;
    const int wid  = t >> 5;
    const int lane = t & 31;
    const int g    = lane >> 2;
    const int c    = lane & 3;
    const int wrow = wid >> 2;
    const int wcol = wid & 3;
    const int m0 = blockIdx.y * 128;
    const int n0 = blockIdx.x * 128;

    const float* aSrc[2]; uint32_t aOff[2];
    const float* bSrc[2]; uint32_t bOff[2];
    #pragma unroll
    for (int s = 0; s < 2; s++) {
        int idx = s * 256 + t;
        int r  = idx >> 2, kq = idx & 3;
        aSrc[s] = A + (size_t)(m0 + r) * K + kq * 4;
        aOff[s] = (r * AS_STRIDE + kq * 4) * 4;
        int kr = idx >> 5, nc = (idx & 31) * 4;
        bSrc[s] = Bm + (size_t)kr * N + n0 + nc;
        bOff[s] = (128 * AS_STRIDE + kr * BS_STRIDE + nc) * 4;
    }

    float acc[4][4][4];
    #pragma unroll
    for (int i = 0; i < 4; i++)
        #pragma unroll
        for (int j = 0; j < 4; j++)
            #pragma unroll
            for (int r = 0; r < 4; r++) acc[i][j][r] = 0.0f;

    const int NIT = K >> 4;

    #pragma unroll
    for (int p = 0; p < 3; p++) {
        uint32_t sb = sbase + p * (STAGE_WORDS * 4);
        #pragma unroll
        for (int s = 0; s < 2; s++) {
            cpa16(sb + aOff[s], aSrc[s] + p * 16);
            cpa16(sb + bOff[s], bSrc[s] + (size_t)p * 16 * N);
        }
        cpa_commit();
    }

    for (int i = 0; i < NIT; i++) {
        cpa_wait2();
        __syncthreads();

        {
            int nt = i + 3;
            uint32_t sb = sbase + (nt & 3) * (STAGE_WORDS * 4);
            if (nt < NIT) {
                #pragma unroll
                for (int s = 0; s < 2; s++) {
                    cpa16(sb + aOff[s], aSrc[s] + nt * 16);
                    cpa16(sb + bOff[s], bSrc[s] + (size_t)nt * 16 * N);
                }
            }
            cpa_commit();
        }

        const uint32_t stw = (i & 3) * STAGE_WORDS;
        unsigned* As = smem + stw;
        unsigned* Bs = smem + stw + 128 * AS_STRIDE;
        #pragma unroll
        for (int ks = 0; ks < 2; ks++) {
            const int kb = ks * 8;
            unsigned a[4][4];
            #pragma unroll
            for (int mt = 0; mt < 4; mt++) {
                const int mb = wrow * 64 + mt * 16;
                a[mt][0] = As[(mb + g)     * AS_STRIDE + kb + c];
                a[mt][1] = As[(mb + g + 8) * AS_STRIDE + kb + c];
                a[mt][2] = As[(mb + g)     * AS_STRIDE + kb + c + 4];
                a[mt][3] = As[(mb + g + 8) * AS_STRIDE + kb + c + 4];
            }
            #pragma unroll
            for (int nt = 0; nt < 4; nt++) {
                const int nb = wcol * 32 + nt * 8 + g;
                unsigned b[2];
                b[0] = Bs[(kb + c)     * BS_STRIDE + nb];
                b[1] = Bs[(kb + c + 4) * BS_STRIDE + nb];
                #pragma unroll
                for (int mt = 0; mt < 4; mt++)
                    mma_tf32(acc[mt][nt], a[mt], b);
            }
        }
    }

    #pragma unroll
    for (int mt = 0; mt < 4; mt++) {
        #pragma unroll
        for (int nt = 0; nt < 4; nt++) {
            const int col = n0 + wcol * 32 + nt * 8 + 2 * c;
            #pragma unroll
            for (int half = 0; half < 2; half++) {
                const int row = m0 + wrow * 64 + mt * 16 + g + half * 8;
                float v0 = acc[mt][nt][half * 2 + 0] + bias[col];
                float v1 = acc[mt][nt][half * 2 + 1] + bias[col + 1];
                if (mode == 0) {
                    float2 o = make_float2(v0, v1);
                    *(float2*)(C + (size_t)row * N + col) = o;
                } else {
                    const int b = row >> 11;
                    const int s = row & (SEQ - 1);
                    const int h = col >> 7;
                    const int d = col & 127;
                    if (mode == 1) {
                        float sn = g_sin[s * HD + d];
                        float cs = g_cos[s * HD + d];
                        float o0 = v0 * cs - v1 * sn;
                        float o1 = v1 * cs + v0 * sn;
                        v0 = o0; v1 = o1;
                    }
                    size_t oidx = ((size_t)((b * NH + h) * SEQ + s)) * HD + d;
                    float2 o = make_float2(__uint_as_float(f2tf(v0)),
                                           __uint_as_float(f2tf(v1)));
                    *(float2*)(&C[oidx]) = o;
                }
            }
        }
    }
}

__global__ __launch_bounds__(256, 2) void qkv_gemm(
    const float* __restrict__ bq, const float* __restrict__ bk,
    const float* __restrict__ bv)
{
    extern __shared__ unsigned smem[];
    const float* Bm; const float* bias; float* C; int mode;
    if (blockIdx.z == 0)      { Bm = g_wq; bias = bq; C = g_q; mode = 1; }
    else if (blockIdx.z == 1) { Bm = g_wk; bias = bk; C = g_k; mode = 1; }
    else                      { Bm = g_wv; bias = bv; C = g_v; mode = 2; }
    gemm_body(mode, g_xtf, Bm, bias, C, smem, HID, HID);
}

__global__ __launch_bounds__(256, 2) void gemm_o(
    const float* __restrict__ A, const float* __restrict__ Bm,
    const float* __restrict__ bias, float* __restrict__ C)
{
    extern __shared__ unsigned smem[];
    gemm_body(0, A, Bm, bias, C, smem, HID, HID);
}

// -------- Flash attention: Br=64, Bc=64, 256 thr, 2 CTAs/SM ---------------
// Q/K/V 64x128 tiles (single-buffered), P 64x64. XOR-quad swizzles:
//   Q/K/P rows: word ^= (row&7)<<2 ; V rows: word ^= (row&3)<<3
#define ATT_Q 0
#define ATT_K (ATT_Q + 64*128)           // 8192
#define ATT_V (ATT_K + 64*128)           // 16384
#define ATT_P (ATT_V + 64*128)           // 24576
#define ATT_M (ATT_P + 64*64)            // 28672
#define ATT_L (ATT_M + 64)
#define ATT_F (ATT_L + 64)
#define ATT_TOT (ATT_F + 64)             // 28864 words
#define SMEM_ATTN_BYTES (ATT_TOT * 4)    // 115456

__global__ __launch_bounds__(256, 2) void attn_kernel() {
    extern __shared__ unsigned sm[];
    const uint32_t sbase = smem_u32(sm);
    unsigned* Qs = sm + ATT_Q;
    unsigned* Ks = sm + ATT_K;
    unsigned* Vs = sm + ATT_V;
    unsigned* Ps = sm + ATT_P;
    float* mrow = (float*)(sm + ATT_M);
    float* lrow = (float*)(sm + ATT_L);
    float* frow = (float*)(sm + ATT_F);

    const int t    = threadIdx.x;
    const int wid  = t >> 5;
    const int lane = t & 31;
    const int g    = lane >> 2;
    const int c    = lane & 3;
    const int gx   = g << 2;
    const int cx   = c << 3;
    const int wrow = wid >> 2;    // 0..1 : 32-row bands
    const int wcol = wid & 3;     // 0..3

    const int q0 = blockIdx.x * 64;
    const int h  = blockIdx.y;
    const int b  = blockIdx.z;
    const size_t bh_off = (size_t)(b * NH + h) * SEQ * HD;
    const float* qg = g_q + bh_off;
    const float* kg = g_k + bh_off;
    const float* vg = g_v + bh_off;

    // ---- prologue: async Q + K(0) + V(0) ----
    #pragma unroll
    for (int p = 0; p < 8; p++) {
        int lin = (p * 256 + t) * 4;
        int r = lin >> 7, w = lin & 127;
        cpa16(sbase + (ATT_Q + r * 128 + (w ^ ((r & 7) << 2))) * 4,
              qg + (size_t)(q0 + r) * HD + w);
        cpa16(sbase + (ATT_K + r * 128 + (w ^ ((r & 7) << 2))) * 4,
              kg + (size_t)r * HD + w);
        cpa16(sbase + (ATT_V + r * 128 + (w ^ ((r & 3) << 3))) * 4,
              vg + (size_t)r * HD + w);
    }
    cpa_commit();

    if (t < 64) { mrow[t] = -INFINITY; lrow[t] = 0.0f; }

    float oacc[2][4][4];
    #pragma unroll
    for (int i = 0; i < 2; i++)
        #pragma unroll
        for (int j = 0; j < 4; j++)
            #pragma unroll
            for (int r = 0; r < 4; r++) oacc[i][j][r] = 0.0f;

    const float scale = 0.08838834764831845f;
    const int srow = t >> 2;   // 0..63
    const int sseg = t & 3;
    const int sx   = (srow & 7) << 2;

    cpa_wait0();
    __syncthreads();

    for (int it = 0; it < SEQ / 64; it++) {
        // ---- S = Q @ K^T (warp tile 32x16) ----
        float sacc[2][2][4];
        #pragma unroll
        for (int i = 0; i < 2; i++)
            #pragma unroll
            for (int j = 0; j < 2; j++)
                #pragma unroll
                for (int r = 0; r < 4; r++) sacc[i][j][r] = 0.0f;

        #pragma unroll 4
        for (int ks = 0; ks < 16; ks++) {
            const int kb = ks * 8;
            const int k0s = (kb ^ gx) | c;
            const int k1s = ((kb + 4) ^ gx) | c;
            unsigned a[2][4];
            #pragma unroll
            for (int mt = 0; mt < 2; mt++) {
                const int mb = wrow * 32 + mt * 16;
                a[mt][0] = Qs[(mb + g)     * 128 + k0s];
                a[mt][1] = Qs[(mb + g + 8) * 128 + k0s];
                a[mt][2] = Qs[(mb + g)     * 128 + k1s];
                a[mt][3] = Qs[(mb + g + 8) * 128 + k1s];
            }
            #pragma unroll
            for (int nt = 0; nt < 2; nt++) {
                const int nb = wcol * 16 + nt * 8 + g;
                unsigned bb[2];
                bb[0] = Ks[nb * 128 + k0s];
                bb[1] = Ks[nb * 128 + k1s];
                #pragma unroll
                for (int mt = 0; mt < 2; mt++)
                    mma_tf32(sacc[mt][nt], a[mt], bb);
            }
        }

        // ---- store scaled logits to Ps (swizzled) ----
        #pragma unroll
        for (int mt = 0; mt < 2; mt++) {
            #pragma unroll
            for (int nt = 0; nt < 2; nt++) {
                const int col = (wcol * 16 + nt * 8 + 2 * c) ^ gx;
                #pragma unroll
                for (int half = 0; half < 2; half++) {
                    const int row = wrow * 32 + mt * 16 + g + half * 8;
                    float2 o = make_float2(sacc[mt][nt][half*2+0] * scale,
                                           sacc[mt][nt][half*2+1] * scale);
                    *(float2*)(&Ps[row * 64 + col]) = o;
                }
            }
        }
        __syncthreads();

        // ---- online softmax: 4 lanes per row ----
        {
            float* Pf = (float*)Ps;
            float mold = mrow[srow];
            float vals[16];
            float mx = -INFINITY;
            #pragma unroll
            for (int i = 0; i < 16; i++) {
                vals[i] = Pf[srow * 64 + ((sseg * 16 + i) ^ sx)];
                mx = fmaxf(mx, vals[i]);
            }
            mx = fmaxf(mx, __shfl_xor_sync(0xffffffffu, mx, 1));
            mx = fmaxf(mx, __shfl_xor_sync(0xffffffffu, mx, 2));
            float mnew = fmaxf(mold, mx);
            float fac = __expf(mold - mnew);
            float psum = 0.0f;
            #pragma unroll
            for (int i = 0; i < 16; i++) {
                float p = __expf(vals[i] - mnew);
                p = __uint_as_float(f2tf(p));
                Pf[srow * 64 + ((sseg * 16 + i) ^ sx)] = p;
                psum += p;
            }
            psum += __shfl_xor_sync(0xffffffffu, psum, 1);
            psum += __shfl_xor_sync(0xffffffffu, psum, 2);
            if (sseg == 0) {
                lrow[srow] = lrow[srow] * fac + psum;
                mrow[srow] = mnew;
                frow[srow] = fac;
            }
        }
        __syncthreads();

        // ---- O = O*fac + P @ V (warp tile 32x32) ----
        #pragma unroll
        for (int mt = 0; mt < 2; mt++) {
            const int mb = wrow * 32 + mt * 16;
            const float f1 = frow[mb + g];
            const float f2 = frow[mb + g + 8];
            #pragma unroll
            for (int nt = 0; nt < 4; nt++) {
                oacc[mt][nt][0] *= f1; oacc[mt][nt][1] *= f1;
                oacc[mt][nt][2] *= f2; oacc[mt][nt][3] *= f2;
            }
        }
        #pragma unroll 2
        for (int ks = 0; ks < 8; ks++) {
            const int kb = ks * 8;
            const int k0s = (kb ^ gx) | c;
            const int k1s = ((kb + 4) ^ gx) | c;
            unsigned a[2][4];
            #pragma unroll
            for (int mt = 0; mt < 2; mt++) {
                const int mb = wrow * 32 + mt * 16;
                a[mt][0] = Ps[(mb + g)     * 64 + k0s];
                a[mt][1] = Ps[(mb + g + 8) * 64 + k0s];
                a[mt][2] = Ps[(mb + g)     * 64 + k1s];
                a[mt][3] = Ps[(mb + g + 8) * 64 + k1s];
            }
            #pragma unroll
            for (int nt = 0; nt < 4; nt++) {
                const int nbv = (wcol * 32 + nt * 8 + g) ^ cx;
                unsigned bb[2];
                bb[0] = Vs[(kb + c)     * 128 + nbv];
                bb[1] = Vs[(kb + c + 4) * 128 + nbv];
                #pragma unroll
                for (int mt = 0; mt < 2; mt++)
                    mma_tf32(oacc[mt][nt], a[mt], bb);
            }
        }
        __syncthreads();

        // ---- load next K/V tile (single-buffered; co-resident CTA hides) --
        if (it + 1 < SEQ / 64) {
            const int nxt = (it + 1) * 64;
            #pragma unroll
            for (int p = 0; p < 8; p++) {
                int lin = (p * 256 + t) * 4;
                int r = lin >> 7, w = lin & 127;
                cpa16(sbase + (ATT_K + r * 128 + (w ^ ((r & 7) << 2))) * 4,
                      kg + (size_t)(nxt + r) * HD + w);
                cpa16(sbase + (ATT_V + r * 128 + (w ^ ((r & 3) << 3))) * 4,
                      vg + (size_t)(nxt + r) * HD + w);
            }
            cpa_commit();
            cpa_wait0();
            __syncthreads();
        }
    }

    // ---- normalize + store to (B,S,H) row-major ----
    #pragma unroll
    for (int mt = 0; mt < 2; mt++) {
        #pragma unroll
        for (int half = 0; half < 2; half++) {
            const int row = wrow * 32 + mt * 16 + g + half * 8;
            const float invl = 1.0f / lrow[row];
            #pragma unroll
            for (int nt = 0; nt < 4; nt++) {
                const int col = wcol * 32 + nt * 8 + 2 * c;
                size_t base = ((size_t)(b * SEQ + q0 + row)) * HID + h * HD + col;
                float2 o;
                o.x = __uint_as_float(f2tf(oacc[mt][nt][half*2+0] * invl));
                o.y = __uint_as_float(f2tf(oacc[mt][nt][half*2+1] * invl));
                *(float2*)(g_att + base) = o;
            }
        }
    }
}

// ---------------------------------------------------------------------------
extern "C" void kernel_launch(void* const* d_in, const int* in_sizes, int n_in,
                              void* d_out, int out_size) {
    const float* X  = (const float*)d_in[0];
    const float* Wq = (const float*)d_in[1];
    const float* bq = (const float*)d_in[2];
    const float* Wk = (const float*)d_in[3];
    const float* bk = (const float*)d_in[4];
    const float* Wv = (const float*)d_in[5];
    const float* bv = (const float*)d_in[6];
    const float* Wo = (const float*)d_in[7];
    const float* bo = (const float*)d_in[8];
    float* out = (float*)d_out;

    float *att, *wo;
    cudaGetSymbolAddress((void**)&att, g_att);
    cudaGetSymbolAddress((void**)&wo,  g_wo);

    cudaFuncSetAttribute(attn_kernel,
                         cudaFuncAttributeMaxDynamicSharedMemorySize, SMEM_ATTN_BYTES);
    cudaFuncSetAttribute(qkv_gemm,
                         cudaFuncAttributeMaxDynamicSharedMemorySize, GSMEM_BYTES);
    cudaFuncSetAttribute(gemm_o,
                         cudaFuncAttributeMaxDynamicSharedMemorySize, GSMEM_BYTES);

    rope_table_kernel<<<(SEQ * HD + 255) / 256, 256>>>();
    cvt_all_kernel<<<8192 + 4 * 4096, 256>>>(X, Wq, Wk, Wv, Wo);

    dim3 gg(HID / 128, MROWS / 128, 3);
    qkv_gemm<<<gg, 256, GSMEM_BYTES>>>(bq, bk, bv);

    attn_kernel<<<dim3(SEQ / 64, NH, BATCH), 256, SMEM_ATTN_BYTES>>>();

    dim3 go(HID / 128, MROWS / 128);
    gemm_o<<<go, 256, GSMEM_BYTES>>>(att, wo, bo, out);
}

// round 13
// speedup vs baseline: 4.6556x; 1.2495x over previous
#include <cuda_runtime.h>
#include <cuda_fp16.h>
#include <math.h>
#include <stdint.h>

#define BATCH 2
#define SEQ   2048
#define HID   2048
#define NH    16
#define HD    128
#define MROWS (BATCH*SEQ)   // 4096

// -------- scratch (static device globals, all half now) --------------------
__device__ __half g_qh[BATCH*NH*SEQ*HD];   // rope applied
__device__ __half g_kh[BATCH*NH*SEQ*HD];
__device__ __half g_vh[BATCH*NH*SEQ*HD];
__device__ __half g_atth[MROWS*HID];
__device__ __half g_xh[MROWS*HID];
__device__ __half g_wqT[HID*HID];          // W^T [N][K]
__device__ __half g_wkT[HID*HID];
__device__ __half g_wvT[HID*HID];
__device__ __half g_woT[HID*HID];
__device__ float  g_sin[SEQ*HD];
__device__ float  g_cos[SEQ*HD];

// -------- helpers ----------------------------------------------------------
__device__ __forceinline__ uint32_t smem_u32(const void* p) {
    uint32_t a;
    asm("{ .reg .u64 t; cvta.to.shared.u64 t, %1; cvt.u32.u64 %0, t; }"
        : "=r"(a) : "l"(p));
    return a;
}

__device__ __forceinline__ void cpa16(uint32_t dst, const void* src) {
    asm volatile(
        "{ .reg .u64 ga; cvta.to.global.u64 ga, %1;"
        "  cp.async.cg.shared.global [%0], [ga], 16; }"
        :: "r"(dst), "l"(src) : "memory");
}
__device__ __forceinline__ void cpa_commit() {
    asm volatile("cp.async.commit_group;" ::: "memory");
}
__device__ __forceinline__ void cpa_wait1() {
    asm volatile("cp.async.wait_group 1;" ::: "memory");
}
__device__ __forceinline__ void cpa_wait2() {
    asm volatile("cp.async.wait_group 2;" ::: "memory");
}

__device__ __forceinline__ void mma_f16(float* d, const unsigned* a, const unsigned* b) {
    asm volatile(
        "mma.sync.aligned.m16n8k16.row.col.f32.f16.f16.f32 "
        "{%0,%1,%2,%3}, {%4,%5,%6,%7}, {%8,%9}, {%0,%1,%2,%3};"
        : "+f"(d[0]), "+f"(d[1]), "+f"(d[2]), "+f"(d[3])
        : "r"(a[0]), "r"(a[1]), "r"(a[2]), "r"(a[3]), "r"(b[0]), "r"(b[1]));
}

__device__ __forceinline__ void ldsm4(unsigned* r, uint32_t addr) {
    asm volatile("ldmatrix.sync.aligned.m8n8.x4.shared.b16 {%0,%1,%2,%3}, [%4];"
        : "=r"(r[0]), "=r"(r[1]), "=r"(r[2]), "=r"(r[3]) : "r"(addr));
}
__device__ __forceinline__ void ldsm4t(unsigned* r, uint32_t addr) {
    asm volatile("ldmatrix.sync.aligned.m8n8.x4.trans.shared.b16 {%0,%1,%2,%3}, [%4];"
        : "=r"(r[0]), "=r"(r[1]), "=r"(r[2]), "=r"(r[3]) : "r"(addr));
}

// -------- RoPE table -------------------------------------------------------
__global__ void rope_table_kernel() {
    int idx = blockIdx.x * blockDim.x + threadIdx.x;
    if (idx >= SEQ*HD) return;
    int s = idx >> 7;
    int d = idx & 127;
    int j = d >> 1;
    float inv = (float)exp(-2.0 * (double)j / 128.0 * log(10000.0));
    float ang = (float)s * inv;
    g_sin[idx] = (float)sin((double)ang);
    g_cos[idx] = (float)cos((double)ang);
}

// -------- X -> half --------------------------------------------------------
__global__ void cvt_x_kernel(const float* __restrict__ X) {
    int i = (blockIdx.x * blockDim.x + threadIdx.x) * 8;
    float4 v0 = *(const float4*)(X + i);
    float4 v1 = *(const float4*)(X + i + 4);
    __half2 h[4];
    h[0] = __floats2half2_rn(v0.x, v0.y);
    h[1] = __floats2half2_rn(v0.z, v0.w);
    h[2] = __floats2half2_rn(v1.x, v1.y);
    h[3] = __floats2half2_rn(v1.z, v1.w);
    *(uint4*)(g_xh + i) = *(uint4*)h;
}

// -------- W [K][N] -> W^T [N][K] half, all 4 weights -----------------------
__global__ void wtrans_kernel(const float* __restrict__ Wq, const float* __restrict__ Wk,
                              const float* __restrict__ Wv, const float* __restrict__ Wo) {
    __shared__ float tile[32][33];
    const float* src; __half* dst;
    if (blockIdx.z == 0)      { src = Wq; dst = g_wqT; }
    else if (blockIdx.z == 1) { src = Wk; dst = g_wkT; }
    else if (blockIdx.z == 2) { src = Wv; dst = g_wvT; }
    else                      { src = Wo; dst = g_woT; }
    const int bx = blockIdx.x * 32;   // N
    const int by = blockIdx.y * 32;   // K
    const int tx = threadIdx.x, ty = threadIdx.y;
    #pragma unroll
    for (int j = 0; j < 32; j += 8)
        tile[ty + j][tx] = src[(size_t)(by + ty + j) * HID + bx + tx];
    __syncthreads();
    #pragma unroll
    for (int j = 0; j < 32; j += 8)
        dst[(size_t)(bx + ty + j) * HID + by + tx] = __float2half(tile[tx][ty + j]);
}

// -------- FP16 mma GEMM: C = A[M,K] @ Bt[N,K]^T + bias ---------------------
// mode 0: float row-major out; mode 1: [b][h][s][d] + RoPE half out;
// mode 2: [b][h][s][d] half out. Tile 128x128, BK=32, 4-stage cp.async.
#define AS_STRIDE 20                   // words per row (16 data + 4 pad)
#define A_WORDS (128*AS_STRIDE)        // 2560
#define STAGE_WORDS (2*A_WORDS)        // 5120
#define GSMEM_BYTES (4*STAGE_WORDS*4)  // 81920

__device__ __forceinline__ void gemm_body_h(
    const int mode,
    const __half* __restrict__ A, const __half* __restrict__ Bt,
    const float* __restrict__ bias, void* __restrict__ Cv,
    unsigned* smem, const int N, const int K)
{
    const uint32_t sbase = smem_u32(smem);
    const int t = threadIdx.x, wid = t >> 5, lane = t & 31;
    const int g = lane >> 2, c = lane & 3;
    const int wrow = wid >> 2, wcol = wid & 3;
    const int m0 = blockIdx.y * 128, n0 = blockIdx.x * 128;

    // ldmatrix lane constants
    const int lm15  = lane & 15;
    const int lmsel = (lane & 16) ? 4 : 0;               // A col word sel
    const int brow  = (lane & 7) + ((lane & 16) ? 8 : 0);
    const int bsel  = (lane & 8) ? 4 : 0;                // B col word sel

    const __half* aSrc[2]; uint32_t aOff[2];
    const __half* bSrc[2]; uint32_t bOff[2];
    #pragma unroll
    for (int s = 0; s < 2; s++) {
        int idx = s * 256 + t;
        int r = idx >> 2, kq = idx & 3;
        aSrc[s] = A  + (size_t)(m0 + r) * K + kq * 8;
        aOff[s] = (r * AS_STRIDE + kq * 4) * 4;
        bSrc[s] = Bt + (size_t)(n0 + r) * K + kq * 8;
        bOff[s] = (A_WORDS + r * AS_STRIDE + kq * 4) * 4;
    }

    float acc[4][4][4];
    #pragma unroll
    for (int i = 0; i < 4; i++)
        #pragma unroll
        for (int j = 0; j < 4; j++)
            #pragma unroll
            for (int r = 0; r < 4; r++) acc[i][j][r] = 0.0f;

    const int NIT = K >> 5;   // 64

    #pragma unroll
    for (int p = 0; p < 3; p++) {
        uint32_t sb = sbase + p * (STAGE_WORDS * 4);
        #pragma unroll
        for (int s = 0; s < 2; s++) {
            cpa16(sb + aOff[s], aSrc[s] + p * 32);
            cpa16(sb + bOff[s], bSrc[s] + p * 32);
        }
        cpa_commit();
    }

    for (int i = 0; i < NIT; i++) {
        cpa_wait2();
        __syncthreads();

        {
            int nt2 = i + 3;
            uint32_t sb = sbase + (nt2 & 3) * (STAGE_WORDS * 4);
            if (nt2 < NIT) {
                #pragma unroll
                for (int s = 0; s < 2; s++) {
                    cpa16(sb + aOff[s], aSrc[s] + nt2 * 32);
                    cpa16(sb + bOff[s], bSrc[s] + nt2 * 32);
                }
            }
            cpa_commit();
        }

        const uint32_t sA = sbase + (i & 3) * (STAGE_WORDS * 4);
        const uint32_t sB = sA + A_WORDS * 4;
        #pragma unroll
        for (int ks = 0; ks < 2; ks++) {
            unsigned af[4][4], bf[2][4];
            #pragma unroll
            for (int mt = 0; mt < 4; mt++)
                ldsm4(af[mt], sA + ((wrow*64 + mt*16 + lm15) * AS_STRIDE + ks*8 + lmsel) * 4);
            #pragma unroll
            for (int np = 0; np < 2; np++)
                ldsm4(bf[np], sB + ((wcol*32 + np*16 + brow) * AS_STRIDE + ks*8 + bsel) * 4);
            #pragma unroll
            for (int np = 0; np < 2; np++)
                #pragma unroll
                for (int mt = 0; mt < 4; mt++) {
                    mma_f16(acc[mt][np*2 + 0], af[mt], &bf[np][0]);
                    mma_f16(acc[mt][np*2 + 1], af[mt], &bf[np][2]);
                }
        }
    }

    // Epilogue
    #pragma unroll
    for (int mt = 0; mt < 4; mt++) {
        #pragma unroll
        for (int nt = 0; nt < 4; nt++) {
            const int col = n0 + wcol * 32 + nt * 8 + 2 * c;
            #pragma unroll
            for (int half_ = 0; half_ < 2; half_++) {
                const int row = m0 + wrow * 64 + mt * 16 + g + half_ * 8;
                float v0 = acc[mt][nt][half_ * 2 + 0] + bias[col];
                float v1 = acc[mt][nt][half_ * 2 + 1] + bias[col + 1];
                if (mode == 0) {
                    float* C = (float*)Cv;
                    float2 o = make_float2(v0, v1);
                    *(float2*)(C + (size_t)row * N + col) = o;
                } else {
                    const int b = row >> 11;
                    const int s = row & (SEQ - 1);
                    const int h = col >> 7;
                    const int d = col & 127;
                    if (mode == 1) {
                        float sn = g_sin[s * HD + d];
                        float cs = g_cos[s * HD + d];
                        float o0 = v0 * cs - v1 * sn;
                        float o1 = v1 * cs + v0 * sn;
                        v0 = o0; v1 = o1;
                    }
                    size_t oidx = ((size_t)((b * NH + h) * SEQ + s)) * HD + d;
                    __half2 hv = __floats2half2_rn(v0, v1);
                    *(__half2*)((__half*)Cv + oidx) = hv;
                }
            }
        }
    }
}

__global__ __launch_bounds__(256, 2) void qkv_gemm(
    const float* __restrict__ bq, const float* __restrict__ bk,
    const float* __restrict__ bv)
{
    extern __shared__ unsigned smem[];
    const __half* Bt; const float* bias; __half* C; int mode;
    if (blockIdx.z == 0)      { Bt = g_wqT; bias = bq; C = g_qh; mode = 1; }
    else if (blockIdx.z == 1) { Bt = g_wkT; bias = bk; C = g_kh; mode = 1; }
    else                      { Bt = g_wvT; bias = bv; C = g_vh; mode = 2; }
    gemm_body_h(mode, g_xh, Bt, bias, C, smem, HID, HID);
}

__global__ __launch_bounds__(256, 2) void gemm_o(
    const float* __restrict__ bo, float* __restrict__ out)
{
    extern __shared__ unsigned smem[];
    gemm_body_h(0, g_atth, g_woT, bo, out, smem, HID, HID);
}

// -------- Flash attention fp16: Br=64, Bc=64, 256 thr, 2 CTAs/SM ----------
// Half tiles [64][64 words]; K/V double-buffered. Logits fp32, P half.
// Swizzle everywhere: word ^= ((row&7)<<2).
#define ATQ  0                       // 4096 words
#define ATK  4096                    // 2 x 4096
#define ATV  12288                   // 2 x 4096
#define ATPF 20480                   // 4096 (fp32 logits [64][64])
#define ATPH 24576                   // 2048 (half P [64][32 words])
#define ATM  26624
#define ATL  26688
#define ATF  26752
#define ATT_TOT 26816
#define ASMEM_BYTES (ATT_TOT * 4)    // 107264

__global__ __launch_bounds__(256, 2) void attn_kernel() {
    extern __shared__ unsigned sm[];
    const uint32_t sbase = smem_u32(sm);
    float* Pf   = (float*)(sm + ATPF);
    unsigned* Ph = sm + ATPH;
    float* mrow = (float*)(sm + ATM);
    float* lrow = (float*)(sm + ATL);
    float* frow = (float*)(sm + ATF);

    const int t = threadIdx.x, wid = t >> 5, lane = t & 31;
    const int g = lane >> 2, c = lane & 3;
    const int wrow = wid >> 2, wcol = wid & 3;

    const int lm15  = lane & 15;
    const int lmsel = (lane & 16) ? 4 : 0;
    const int krow  = (lane & 7) + ((lane & 16) ? 8 : 0);
    const int ksel  = (lane & 8) ? 4 : 0;
    const int vsel  = (lane & 16) ? 4 : 0;
    const int lsw   = (lane & 7) << 2;       // row&7 swizzle, all fragment reads
    const int gx    = g << 2;                // S-store swizzle (row&7 == g)

    const int q0 = blockIdx.x * 64;
    const int h  = blockIdx.y;
    const int b  = blockIdx.z;
    const size_t bh_off = (size_t)(b * NH + h) * SEQ * HD;
    const __half* qg = g_qh + bh_off;
    const __half* kg = g_kh + bh_off;
    const __half* vg = g_vh + bh_off;

    // prologue: G0 = Q + K0 + V0 ; G1 = K1 + V1
    #pragma unroll
    for (int p = 0; p < 4; p++) {
        int lin = p * 256 + t;
        int r = lin >> 4, c4 = lin & 15;
        uint32_t swz = ((c4 * 4) ^ ((r & 7) << 2));
        cpa16(sbase + (ATQ + r * 64 + swz) * 4, qg + (size_t)(q0 + r) * HD + c4 * 8);
        cpa16(sbase + (ATK + r * 64 + swz) * 4, kg + (size_t)r * HD + c4 * 8);
        cpa16(sbase + (ATV + r * 64 + swz) * 4, vg + (size_t)r * HD + c4 * 8);
    }
    cpa_commit();
    #pragma unroll
    for (int p = 0; p < 4; p++) {
        int lin = p * 256 + t;
        int r = lin >> 4, c4 = lin & 15;
        uint32_t swz = ((c4 * 4) ^ ((r & 7) << 2));
        cpa16(sbase + (ATK + 4096 + r * 64 + swz) * 4, kg + (size_t)(64 + r) * HD + c4 * 8);
        cpa16(sbase + (ATV + 4096 + r * 64 + swz) * 4, vg + (size_t)(64 + r) * HD + c4 * 8);
    }
    cpa_commit();

    if (t < 64) { mrow[t] = -INFINITY; lrow[t] = 0.0f; }

    float oacc[2][4][4];
    #pragma unroll
    for (int i = 0; i < 2; i++)
        #pragma unroll
        for (int j = 0; j < 4; j++)
            #pragma unroll
            for (int r = 0; r < 4; r++) oacc[i][j][r] = 0.0f;

    const float scale = 0.08838834764831845f;
    const int srow = t >> 2;
    const int sseg = t & 3;
    const int sx   = (srow & 7) << 2;

    for (int it = 0; it < SEQ / 64; it++) {
        cpa_wait1();
        __syncthreads();
        const uint32_t kbb = sbase + (ATK + (it & 1) * 4096) * 4;
        const uint32_t vbb = sbase + (ATV + (it & 1) * 4096) * 4;

        // ---- S = Q @ K^T : 8 ksteps of k16, warp tile 32x16 ----
        float sacc[2][2][4];
        #pragma unroll
        for (int i = 0; i < 2; i++)
            #pragma unroll
            for (int j = 0; j < 2; j++)
                #pragma unroll
                for (int r = 0; r < 4; r++) sacc[i][j][r] = 0.0f;

        #pragma unroll 4
        for (int ks = 0; ks < 8; ks++) {
            unsigned aq[2][4], bk2[4];
            #pragma unroll
            for (int mt = 0; mt < 2; mt++)
                ldsm4(aq[mt], sbase + (ATQ + (wrow*32 + mt*16 + lm15) * 64
                                       + ((ks*8 + lmsel) ^ lsw)) * 4);
            ldsm4(bk2, kbb + ((wcol*16 + krow) * 64 + ((ks*8 + ksel) ^ lsw)) * 4);
            #pragma unroll
            for (int mt = 0; mt < 2; mt++) {
                mma_f16(sacc[mt][0], aq[mt], &bk2[0]);
                mma_f16(sacc[mt][1], aq[mt], &bk2[2]);
            }
        }

        // ---- store scaled logits (fp32) ----
        #pragma unroll
        for (int mt = 0; mt < 2; mt++) {
            #pragma unroll
            for (int nt = 0; nt < 2; nt++) {
                const int col = (wcol * 16 + nt * 8 + 2 * c) ^ gx;
                #pragma unroll
                for (int half_ = 0; half_ < 2; half_++) {
                    const int row = wrow * 32 + mt * 16 + g + half_ * 8;
                    float2 o = make_float2(sacc[mt][nt][half_*2+0] * scale,
                                           sacc[mt][nt][half_*2+1] * scale);
                    *(float2*)(&Pf[row * 64 + col]) = o;
                }
            }
        }
        __syncthreads();

        // ---- online softmax: 4 lanes per row, fp32 -> half P ----
        {
            float vals[16];
            float mold = mrow[srow];
            float mx = -INFINITY;
            #pragma unroll
            for (int i = 0; i < 16; i++) {
                vals[i] = Pf[srow * 64 + ((sseg * 16 + i) ^ sx)];
                mx = fmaxf(mx, vals[i]);
            }
            mx = fmaxf(mx, __shfl_xor_sync(0xffffffffu, mx, 1));
            mx = fmaxf(mx, __shfl_xor_sync(0xffffffffu, mx, 2));
            float mnew = fmaxf(mold, mx);
            float fac = __expf(mold - mnew);
            float psum = 0.0f;
            #pragma unroll
            for (int i = 0; i < 16; i++) {
                vals[i] = __expf(vals[i] - mnew);
                psum += vals[i];
            }
            #pragma unroll
            for (int j = 0; j < 8; j++) {
                __half2 hp = __floats2half2_rn(vals[2*j], vals[2*j+1]);
                Ph[srow * 32 + ((sseg * 8 + j) ^ sx)] = *(unsigned*)&hp;
            }
            psum += __shfl_xor_sync(0xffffffffu, psum, 1);
            psum += __shfl_xor_sync(0xffffffffu, psum, 2);
            if (sseg == 0) {
                lrow[srow] = lrow[srow] * fac + psum;
                mrow[srow] = mnew;
                frow[srow] = fac;
            }
        }
        __syncthreads();

        // ---- O = O*fac + P @ V : 4 ksteps of k16, warp tile 32x32 ----
        #pragma unroll
        for (int mt = 0; mt < 2; mt++) {
            const int mb = wrow * 32 + mt * 16;
            const float f1 = frow[mb + g];
            const float f2 = frow[mb + g + 8];
            #pragma unroll
            for (int nt = 0; nt < 4; nt++) {
                oacc[mt][nt][0] *= f1; oacc[mt][nt][1] *= f1;
                oacc[mt][nt][2] *= f2; oacc[mt][nt][3] *= f2;
            }
        }
        #pragma unroll
        for (int ks = 0; ks < 4; ks++) {
            unsigned ap[2][4], bv2[2][4];
            #pragma unroll
            for (int mt = 0; mt < 2; mt++)
                ldsm4(ap[mt], sbase + (ATPH + (wrow*32 + mt*16 + lm15) * 32
                                       + ((ks*8 + lmsel) ^ lsw)) * 4);
            #pragma unroll
            for (int np = 0; np < 2; np++)
                ldsm4t(bv2[np], vbb + ((ks*16 + lm15) * 64
                                       + ((wcol*16 + np*8 + vsel) ^ lsw)) * 4);
            #pragma unroll
            for (int np = 0; np < 2; np++)
                #pragma unroll
                for (int mt = 0; mt < 2; mt++) {
                    mma_f16(oacc[mt][np*2 + 0], ap[mt], &bv2[np][0]);
                    mma_f16(oacc[mt][np*2 + 1], ap[mt], &bv2[np][2]);
                }
        }
        __syncthreads();

        // ---- issue K/V(it+2) into buffer (it&1) ----
        if (it + 2 < SEQ / 64) {
            const int nxt = (it + 2) * 64;
            const uint32_t kd = ATK + (it & 1) * 4096;
            const uint32_t vd = ATV + (it & 1) * 4096;
            #pragma unroll
            for (int p = 0; p < 4; p++) {
                int lin = p * 256 + t;
                int r = lin >> 4, c4 = lin & 15;
                uint32_t swz = ((c4 * 4) ^ ((r & 7) << 2));
                cpa16(sbase + (kd + r * 64 + swz) * 4, kg + (size_t)(nxt + r) * HD + c4 * 8);
                cpa16(sbase + (vd + r * 64 + swz) * 4, vg + (size_t)(nxt + r) * HD + c4 * 8);
            }
            cpa_commit();
        }
    }

    // ---- normalize + store half to att [B,S,H] ----
    #pragma unroll
    for (int mt = 0; mt < 2; mt++) {
        #pragma unroll
        for (int half_ = 0; half_ < 2; half_++) {
            const int row = wrow * 32 + mt * 16 + g + half_ * 8;
            const float invl = 1.0f / lrow[row];
            #pragma unroll
            for (int nt = 0; nt < 4; nt++) {
                const int col = wcol * 32 + nt * 8 + 2 * c;
                size_t base = ((size_t)(b * SEQ + q0 + row)) * HID + h * HD + col;
                __half2 hv = __floats2half2_rn(oacc[mt][nt][half_*2+0] * invl,
                                               oacc[mt][nt][half_*2+1] * invl);
                *(__half2*)(g_atth + base) = hv;
            }
        }
    }
}

// ---------------------------------------------------------------------------
extern "C" void kernel_launch(void* const* d_in, const int* in_sizes, int n_in,
                              void* d_out, int out_size) {
    const float* X  = (const float*)d_in[0];
    const float* Wq = (const float*)d_in[1];
    const float* bq = (const float*)d_in[2];
    const float* Wk = (const float*)d_in[3];
    const float* bk = (const float*)d_in[4];
    const float* Wv = (const float*)d_in[5];
    const float* bv = (const float*)d_in[6];
    const float* Wo = (const float*)d_in[7];
    const float* bo = (const float*)d_in[8];
    float* out = (float*)d_out;

    cudaFuncSetAttribute(attn_kernel,
                         cudaFuncAttributeMaxDynamicSharedMemorySize, ASMEM_BYTES);
    cudaFuncSetAttribute(qkv_gemm,
                         cudaFuncAttributeMaxDynamicSharedMemorySize, GSMEM_BYTES);
    cudaFuncSetAttribute(gemm_o,
                         cudaFuncAttributeMaxDynamicSharedMemorySize, GSMEM_BYTES);

    rope_table_kernel<<<(SEQ * HD) / 256, 256>>>();
    cvt_x_kernel<<<(MROWS * HID / 8) / 256, 256>>>(X);
    wtrans_kernel<<<dim3(HID / 32, HID / 32, 4), dim3(32, 8)>>>(Wq, Wk, Wv, Wo);

    dim3 gg(HID / 128, MROWS / 128, 3);
    qkv_gemm<<<gg, 256, GSMEM_BYTES>>>(bq, bk, bv);

    attn_kernel<<<dim3(SEQ / 64, NH, BATCH), 256, ASMEM_BYTES>>>();

    dim3 go(HID / 128, MROWS / 128);
    gemm_o<<<go, 256, GSMEM_BYTES>>>(bo, out);
}

// round 14
// speedup vs baseline: 5.4014x; 1.1602x over previous
#include <cuda_runtime.h>
#include <cuda_fp16.h>
#include <math.h>
#include <stdint.h>

#define BATCH 2
#define SEQ   2048
#define HID   2048
#define NH    16
#define HD    128
#define MROWS (BATCH*SEQ)   // 4096

// -------- scratch (static device globals, all half) ------------------------
__device__ __half g_qh[BATCH*NH*SEQ*HD];   // rope applied
__device__ __half g_kh[BATCH*NH*SEQ*HD];
__device__ __half g_vh[BATCH*NH*SEQ*HD];
__device__ __half g_atth[MROWS*HID];
__device__ __half g_xh[MROWS*HID];
__device__ __half g_wqT[HID*HID];          // W^T [N][K]
__device__ __half g_wkT[HID*HID];
__device__ __half g_wvT[HID*HID];
__device__ __half g_woT[HID*HID];
__device__ float  g_sin[SEQ*HD];
__device__ float  g_cos[SEQ*HD];

// -------- helpers ----------------------------------------------------------
__device__ __forceinline__ uint32_t smem_u32(const void* p) {
    uint32_t a;
    asm("{ .reg .u64 t; cvta.to.shared.u64 t, %1; cvt.u32.u64 %0, t; }"
        : "=r"(a) : "l"(p));
    return a;
}

__device__ __forceinline__ void cpa16(uint32_t dst, const void* src) {
    asm volatile(
        "{ .reg .u64 ga; cvta.to.global.u64 ga, %1;"
        "  cp.async.cg.shared.global [%0], [ga], 16; }"
        :: "r"(dst), "l"(src) : "memory");
}
__device__ __forceinline__ void cpa_commit() {
    asm volatile("cp.async.commit_group;" ::: "memory");
}
__device__ __forceinline__ void cpa_wait1() {
    asm volatile("cp.async.wait_group 1;" ::: "memory");
}
__device__ __forceinline__ void cpa_wait2() {
    asm volatile("cp.async.wait_group 2;" ::: "memory");
}

__device__ __forceinline__ void mma_f16(float* d, const unsigned* a, const unsigned* b) {
    asm volatile(
        "mma.sync.aligned.m16n8k16.row.col.f32.f16.f16.f32 "
        "{%0,%1,%2,%3}, {%4,%5,%6,%7}, {%8,%9}, {%0,%1,%2,%3};"
        : "+f"(d[0]), "+f"(d[1]), "+f"(d[2]), "+f"(d[3])
        : "r"(a[0]), "r"(a[1]), "r"(a[2]), "r"(a[3]), "r"(b[0]), "r"(b[1]));
}

__device__ __forceinline__ void ldsm4(unsigned* r, uint32_t addr) {
    asm volatile("ldmatrix.sync.aligned.m8n8.x4.shared.b16 {%0,%1,%2,%3}, [%4];"
        : "=r"(r[0]), "=r"(r[1]), "=r"(r[2]), "=r"(r[3]) : "r"(addr));
}
__device__ __forceinline__ void ldsm4t(unsigned* r, uint32_t addr) {
    asm volatile("ldmatrix.sync.aligned.m8n8.x4.trans.shared.b16 {%0,%1,%2,%3}, [%4];"
        : "=r"(r[0]), "=r"(r[1]), "=r"(r[2]), "=r"(r[3]) : "r"(addr));
}

// -------- RoPE table -------------------------------------------------------
__global__ void rope_table_kernel() {
    int idx = blockIdx.x * blockDim.x + threadIdx.x;
    if (idx >= SEQ*HD) return;
    int s = idx >> 7;
    int d = idx & 127;
    int j = d >> 1;
    float inv = (float)exp(-2.0 * (double)j / 128.0 * log(10000.0));
    float ang = (float)s * inv;
    g_sin[idx] = (float)sin((double)ang);
    g_cos[idx] = (float)cos((double)ang);
}

// -------- X -> half --------------------------------------------------------
__global__ void cvt_x_kernel(const float* __restrict__ X) {
    int i = (blockIdx.x * blockDim.x + threadIdx.x) * 8;
    float4 v0 = *(const float4*)(X + i);
    float4 v1 = *(const float4*)(X + i + 4);
    __half2 h[4];
    h[0] = __floats2half2_rn(v0.x, v0.y);
    h[1] = __floats2half2_rn(v0.z, v0.w);
    h[2] = __floats2half2_rn(v1.x, v1.y);
    h[3] = __floats2half2_rn(v1.z, v1.w);
    *(uint4*)(g_xh + i) = *(uint4*)h;
}

// -------- W [K][N] -> W^T [N][K] half, all 4 weights -----------------------
__global__ void wtrans_kernel(const float* __restrict__ Wq, const float* __restrict__ Wk,
                              const float* __restrict__ Wv, const float* __restrict__ Wo) {
    __shared__ float tile[32][33];
    const float* src; __half* dst;
    if (blockIdx.z == 0)      { src = Wq; dst = g_wqT; }
    else if (blockIdx.z == 1) { src = Wk; dst = g_wkT; }
    else if (blockIdx.z == 2) { src = Wv; dst = g_wvT; }
    else                      { src = Wo; dst = g_woT; }
    const int bx = blockIdx.x * 32;   // N
    const int by = blockIdx.y * 32;   // K
    const int tx = threadIdx.x, ty = threadIdx.y;
    #pragma unroll
    for (int j = 0; j < 32; j += 8)
        tile[ty + j][tx] = src[(size_t)(by + ty + j) * HID + bx + tx];
    __syncthreads();
    #pragma unroll
    for (int j = 0; j < 32; j += 8)
        dst[(size_t)(bx + ty + j) * HID + by + tx] = __float2half(tile[tx][ty + j]);
}

// -------- FP16 mma GEMM: C = A[M,K] @ Bt[N,K]^T + bias ---------------------
#define AS_STRIDE 20                   // words per row (16 data + 4 pad)
#define A_WORDS (128*AS_STRIDE)        // 2560
#define STAGE_WORDS (2*A_WORDS)        // 5120
#define GSMEM_BYTES (4*STAGE_WORDS*4)  // 81920

__device__ __forceinline__ void gemm_body_h(
    const int mode,
    const __half* __restrict__ A, const __half* __restrict__ Bt,
    const float* __restrict__ bias, void* __restrict__ Cv,
    unsigned* smem, const int N, const int K)
{
    const uint32_t sbase = smem_u32(smem);
    const int t = threadIdx.x, wid = t >> 5, lane = t & 31;
    const int g = lane >> 2, c = lane & 3;
    const int wrow = wid >> 2, wcol = wid & 3;
    const int m0 = blockIdx.y * 128, n0 = blockIdx.x * 128;

    const int lm15  = lane & 15;
    const int lmsel = (lane & 16) ? 4 : 0;
    const int brow  = (lane & 7) + ((lane & 16) ? 8 : 0);
    const int bsel  = (lane & 8) ? 4 : 0;

    const __half* aSrc[2]; uint32_t aOff[2];
    const __half* bSrc[2]; uint32_t bOff[2];
    #pragma unroll
    for (int s = 0; s < 2; s++) {
        int idx = s * 256 + t;
        int r = idx >> 2, kq = idx & 3;
        aSrc[s] = A  + (size_t)(m0 + r) * K + kq * 8;
        aOff[s] = (r * AS_STRIDE + kq * 4) * 4;
        bSrc[s] = Bt + (size_t)(n0 + r) * K + kq * 8;
        bOff[s] = (A_WORDS + r * AS_STRIDE + kq * 4) * 4;
    }

    float acc[4][4][4];
    #pragma unroll
    for (int i = 0; i < 4; i++)
        #pragma unroll
        for (int j = 0; j < 4; j++)
            #pragma unroll
            for (int r = 0; r < 4; r++) acc[i][j][r] = 0.0f;

    const int NIT = K >> 5;

    #pragma unroll
    for (int p = 0; p < 3; p++) {
        uint32_t sb = sbase + p * (STAGE_WORDS * 4);
        #pragma unroll
        for (int s = 0; s < 2; s++) {
            cpa16(sb + aOff[s], aSrc[s] + p * 32);
            cpa16(sb + bOff[s], bSrc[s] + p * 32);
        }
        cpa_commit();
    }

    for (int i = 0; i < NIT; i++) {
        cpa_wait2();
        __syncthreads();

        {
            int nt2 = i + 3;
            uint32_t sb = sbase + (nt2 & 3) * (STAGE_WORDS * 4);
            if (nt2 < NIT) {
                #pragma unroll
                for (int s = 0; s < 2; s++) {
                    cpa16(sb + aOff[s], aSrc[s] + nt2 * 32);
                    cpa16(sb + bOff[s], bSrc[s] + nt2 * 32);
                }
            }
            cpa_commit();
        }

        const uint32_t sA = sbase + (i & 3) * (STAGE_WORDS * 4);
        const uint32_t sB = sA + A_WORDS * 4;
        #pragma unroll
        for (int ks = 0; ks < 2; ks++) {
            unsigned af[4][4], bf[2][4];
            #pragma unroll
            for (int mt = 0; mt < 4; mt++)
                ldsm4(af[mt], sA + ((wrow*64 + mt*16 + lm15) * AS_STRIDE + ks*8 + lmsel) * 4);
            #pragma unroll
            for (int np = 0; np < 2; np++)
                ldsm4(bf[np], sB + ((wcol*32 + np*16 + brow) * AS_STRIDE + ks*8 + bsel) * 4);
            #pragma unroll
            for (int np = 0; np < 2; np++)
                #pragma unroll
                for (int mt = 0; mt < 4; mt++) {
                    mma_f16(acc[mt][np*2 + 0], af[mt], &bf[np][0]);
                    mma_f16(acc[mt][np*2 + 1], af[mt], &bf[np][2]);
                }
        }
    }

    #pragma unroll
    for (int mt = 0; mt < 4; mt++) {
        #pragma unroll
        for (int nt = 0; nt < 4; nt++) {
            const int col = n0 + wcol * 32 + nt * 8 + 2 * c;
            #pragma unroll
            for (int half_ = 0; half_ < 2; half_++) {
                const int row = m0 + wrow * 64 + mt * 16 + g + half_ * 8;
                float v0 = acc[mt][nt][half_ * 2 + 0] + bias[col];
                float v1 = acc[mt][nt][half_ * 2 + 1] + bias[col + 1];
                if (mode == 0) {
                    float* C = (float*)Cv;
                    float2 o = make_float2(v0, v1);
                    *(float2*)(C + (size_t)row * N + col) = o;
                } else {
                    const int b = row >> 11;
                    const int s = row & (SEQ - 1);
                    const int h = col >> 7;
                    const int d = col & 127;
                    if (mode == 1) {
                        float sn = g_sin[s * HD + d];
                        float cs = g_cos[s * HD + d];
                        float o0 = v0 * cs - v1 * sn;
                        float o1 = v1 * cs + v0 * sn;
                        v0 = o0; v1 = o1;
                    }
                    size_t oidx = ((size_t)((b * NH + h) * SEQ + s)) * HD + d;
                    __half2 hv = __floats2half2_rn(v0, v1);
                    *(__half2*)((__half*)Cv + oidx) = hv;
                }
            }
        }
    }
}

__global__ __launch_bounds__(256, 2) void qkv_gemm(
    const float* __restrict__ bq, const float* __restrict__ bk,
    const float* __restrict__ bv)
{
    extern __shared__ unsigned smem[];
    const __half* Bt; const float* bias; __half* C; int mode;
    if (blockIdx.z == 0)      { Bt = g_wqT; bias = bq; C = g_qh; mode = 1; }
    else if (blockIdx.z == 1) { Bt = g_wkT; bias = bk; C = g_kh; mode = 1; }
    else                      { Bt = g_wvT; bias = bv; C = g_vh; mode = 2; }
    gemm_body_h(mode, g_xh, Bt, bias, C, smem, HID, HID);
}

__global__ __launch_bounds__(256, 2) void gemm_o(
    const float* __restrict__ bo, float* __restrict__ out)
{
    extern __shared__ unsigned smem[];
    gemm_body_h(0, g_atth, g_woT, bo, out, smem, HID, HID);
}

// -------- Flash attention fp16, FA2 layout: Br=128, Bc=64, 256 thr ---------
// 8 warps, each owns 16 full rows. Softmax + P entirely in registers.
// Smem: Q[128][64w] + K 2x[64][64w] + V 2x[64][64w] = 96 KB -> 2 CTAs/SM.
// Swizzle: word ^= ((row&7)<<2).
#define ATQ  0                       // 8192 words
#define ATK  8192                    // 2 x 4096
#define ATV  16384                   // 2 x 4096
#define ATT_TOT 24576
#define ASMEM_BYTES (ATT_TOT * 4)    // 98304

__global__ __launch_bounds__(256, 2) void attn_kernel() {
    extern __shared__ unsigned sm[];
    const uint32_t sbase = smem_u32(sm);

    const int t = threadIdx.x, wid = t >> 5, lane = t & 31;
    const int g = lane >> 2, c = lane & 3;

    const int lm15  = lane & 15;
    const int lmsel = (lane & 16) ? 4 : 0;
    const int krow  = (lane & 7) + ((lane & 16) ? 8 : 0);
    const int ksel  = (lane & 8) ? 4 : 0;
    const int vsel  = (lane & 16) ? 4 : 0;
    const int lsw   = (lane & 7) << 2;

    const int q0 = blockIdx.x * 128;
    const int h  = blockIdx.y;
    const int b  = blockIdx.z;
    const size_t bh_off = (size_t)(b * NH + h) * SEQ * HD;
    const __half* qg = g_qh + bh_off;
    const __half* kg = g_kh + bh_off;
    const __half* vg = g_vh + bh_off;

    // prologue: G0 = Q + K0 + V0 ; G1 = K1 + V1
    #pragma unroll
    for (int p = 0; p < 8; p++) {
        int lin = p * 256 + t;
        int r = lin >> 4, c4 = lin & 15;
        uint32_t swz = ((c4 * 4) ^ ((r & 7) << 2));
        cpa16(sbase + (ATQ + r * 64 + swz) * 4, qg + (size_t)(q0 + r) * HD + c4 * 8);
    }
    #pragma unroll
    for (int p = 0; p < 4; p++) {
        int lin = p * 256 + t;
        int r = lin >> 4, c4 = lin & 15;
        uint32_t swz = ((c4 * 4) ^ ((r & 7) << 2));
        cpa16(sbase + (ATK + r * 64 + swz) * 4, kg + (size_t)r * HD + c4 * 8);
        cpa16(sbase + (ATV + r * 64 + swz) * 4, vg + (size_t)r * HD + c4 * 8);
    }
    cpa_commit();
    #pragma unroll
    for (int p = 0; p < 4; p++) {
        int lin = p * 256 + t;
        int r = lin >> 4, c4 = lin & 15;
        uint32_t swz = ((c4 * 4) ^ ((r & 7) << 2));
        cpa16(sbase + (ATK + 4096 + r * 64 + swz) * 4, kg + (size_t)(64 + r) * HD + c4 * 8);
        cpa16(sbase + (ATV + 4096 + r * 64 + swz) * 4, vg + (size_t)(64 + r) * HD + c4 * 8);
    }
    cpa_commit();

    // per-thread softmax state: rows r0 = wid*16+g, r1 = r0+8 (scaled domain)
    float m0 = -INFINITY, m1 = -INFINITY;
    float l0 = 0.0f, l1 = 0.0f;

    float oacc[16][4];   // 16 n8-tiles over 128 cols
    #pragma unroll
    for (int i = 0; i < 16; i++)
        #pragma unroll
        for (int r = 0; r < 4; r++) oacc[i][r] = 0.0f;

    const float scale = 0.08838834764831845f;
    const uint32_t qrow_base = sbase + (ATQ + (wid * 16 + lm15) * 64) * 4;

    for (int it = 0; it < SEQ / 64; it++) {
        cpa_wait1();
        __syncthreads();
        const uint32_t kbb = sbase + (ATK + (it & 1) * 4096) * 4;
        const uint32_t vbb = sbase + (ATV + (it & 1) * 4096) * 4;

        // ---- S = Q @ K^T : warp tile 16x64, 8 ksteps of k16 ----
        float sacc[8][4];
        #pragma unroll
        for (int i = 0; i < 8; i++)
            #pragma unroll
            for (int r = 0; r < 4; r++) sacc[i][r] = 0.0f;

        #pragma unroll 4
        for (int ks = 0; ks < 8; ks++) {
            unsigned aq[4];
            ldsm4(aq, qrow_base + (((ks * 8 + lmsel) ^ lsw)) * 4);
            #pragma unroll
            for (int nn = 0; nn < 4; nn++) {
                unsigned bk2[4];
                ldsm4(bk2, kbb + ((nn * 16 + krow) * 64 + ((ks * 8 + ksel) ^ lsw)) * 4);
                mma_f16(sacc[nn * 2 + 0], aq, &bk2[0]);
                mma_f16(sacc[nn * 2 + 1], aq, &bk2[2]);
            }
        }

        // ---- register softmax: rows r0 (vals 0,1), r1 (vals 2,3) ----
        float mx0 = -INFINITY, mx1 = -INFINITY;
        #pragma unroll
        for (int nt = 0; nt < 8; nt++) {
            mx0 = fmaxf(mx0, fmaxf(sacc[nt][0], sacc[nt][1]));
            mx1 = fmaxf(mx1, fmaxf(sacc[nt][2], sacc[nt][3]));
        }
        mx0 = fmaxf(mx0, __shfl_xor_sync(0xffffffffu, mx0, 1));
        mx0 = fmaxf(mx0, __shfl_xor_sync(0xffffffffu, mx0, 2));
        mx1 = fmaxf(mx1, __shfl_xor_sync(0xffffffffu, mx1, 1));
        mx1 = fmaxf(mx1, __shfl_xor_sync(0xffffffffu, mx1, 2));
        const float mn0 = fmaxf(m0, mx0 * scale);
        const float mn1 = fmaxf(m1, mx1 * scale);
        const float f0 = __expf(m0 - mn0);
        const float f1 = __expf(m1 - mn1);
        float ps0 = 0.0f, ps1 = 0.0f;
        #pragma unroll
        for (int nt = 0; nt < 8; nt++) {
            sacc[nt][0] = __expf(sacc[nt][0] * scale - mn0);
            sacc[nt][1] = __expf(sacc[nt][1] * scale - mn0);
            sacc[nt][2] = __expf(sacc[nt][2] * scale - mn1);
            sacc[nt][3] = __expf(sacc[nt][3] * scale - mn1);
            ps0 += sacc[nt][0] + sacc[nt][1];
            ps1 += sacc[nt][2] + sacc[nt][3];
        }
        ps0 += __shfl_xor_sync(0xffffffffu, ps0, 1);
        ps0 += __shfl_xor_sync(0xffffffffu, ps0, 2);
        ps1 += __shfl_xor_sync(0xffffffffu, ps1, 1);
        ps1 += __shfl_xor_sync(0xffffffffu, ps1, 2);
        l0 = l0 * f0 + ps0;  m0 = mn0;
        l1 = l1 * f1 + ps1;  m1 = mn1;

        // ---- P fragments (C-of-S == A-of-PV identity), then rescale O ----
        unsigned pa[4][4];
        #pragma unroll
        for (int ks = 0; ks < 4; ks++) {
            __half2 h0 = __floats2half2_rn(sacc[2*ks][0],   sacc[2*ks][1]);
            __half2 h1 = __floats2half2_rn(sacc[2*ks][2],   sacc[2*ks][3]);
            __half2 h2 = __floats2half2_rn(sacc[2*ks+1][0], sacc[2*ks+1][1]);
            __half2 h3 = __floats2half2_rn(sacc[2*ks+1][2], sacc[2*ks+1][3]);
            pa[ks][0] = *(unsigned*)&h0;
            pa[ks][1] = *(unsigned*)&h1;
            pa[ks][2] = *(unsigned*)&h2;
            pa[ks][3] = *(unsigned*)&h3;
        }
        #pragma unroll
        for (int nt = 0; nt < 16; nt++) {
            oacc[nt][0] *= f0; oacc[nt][1] *= f0;
            oacc[nt][2] *= f1; oacc[nt][3] *= f1;
        }

        // ---- O += P @ V : 4 ksteps of k16 over 128 cols ----
        #pragma unroll
        for (int ks = 0; ks < 4; ks++) {
            #pragma unroll
            for (int nn = 0; nn < 8; nn++) {
                unsigned bv2[4];
                ldsm4t(bv2, vbb + ((ks * 16 + lm15) * 64 + ((nn * 8 + vsel) ^ lsw)) * 4);
                mma_f16(oacc[nn * 2 + 0], pa[ks], &bv2[0]);
                mma_f16(oacc[nn * 2 + 1], pa[ks], &bv2[2]);
            }
        }
        __syncthreads();

        // ---- issue K/V(it+2) into buffer (it&1) ----
        if (it + 2 < SEQ / 64) {
            const int nxt = (it + 2) * 64;
            const uint32_t kd = ATK + (it & 1) * 4096;
            const uint32_t vd = ATV + (it & 1) * 4096;
            #pragma unroll
            for (int p = 0; p < 4; p++) {
                int lin = p * 256 + t;
                int r = lin >> 4, c4 = lin & 15;
                uint32_t swz = ((c4 * 4) ^ ((r & 7) << 2));
                cpa16(sbase + (kd + r * 64 + swz) * 4, kg + (size_t)(nxt + r) * HD + c4 * 8);
                cpa16(sbase + (vd + r * 64 + swz) * 4, vg + (size_t)(nxt + r) * HD + c4 * 8);
            }
            cpa_commit();
        }
    }

    // ---- normalize + store half to att [B,S,H] ----
    const float il0 = 1.0f / l0;
    const float il1 = 1.0f / l1;
    const int r0 = wid * 16 + g;
    #pragma unroll
    for (int nt = 0; nt < 16; nt++) {
        const int col = nt * 8 + 2 * c;
        size_t base0 = ((size_t)(b * SEQ + q0 + r0)) * HID + h * HD + col;
        size_t base1 = base0 + (size_t)8 * HID;
        __half2 h0 = __floats2half2_rn(oacc[nt][0] * il0, oacc[nt][1] * il0);
        __half2 h1 = __floats2half2_rn(oacc[nt][2] * il1, oacc[nt][3] * il1);
        *(__half2*)(g_atth + base0) = h0;
        *(__half2*)(g_atth + base1) = h1;
    }
}

// ---------------------------------------------------------------------------
extern "C" void kernel_launch(void* const* d_in, const int* in_sizes, int n_in,
                              void* d_out, int out_size) {
    const float* X  = (const float*)d_in[0];
    const float* Wq = (const float*)d_in[1];
    const float* bq = (const float*)d_in[2];
    const float* Wk = (const float*)d_in[3];
    const float* bk = (const float*)d_in[4];
    const float* Wv = (const float*)d_in[5];
    const float* bv = (const float*)d_in[6];
    const float* Wo = (const float*)d_in[7];
    const float* bo = (const float*)d_in[8];
    float* out = (float*)d_out;

    cudaFuncSetAttribute(attn_kernel,
                         cudaFuncAttributeMaxDynamicSharedMemorySize, ASMEM_BYTES);
    cudaFuncSetAttribute(qkv_gemm,
                         cudaFuncAttributeMaxDynamicSharedMemorySize, GSMEM_BYTES);
    cudaFuncSetAttribute(gemm_o,
                         cudaFuncAttributeMaxDynamicSharedMemorySize, GSMEM_BYTES);

    rope_table_kernel<<<(SEQ * HD) / 256, 256>>>();
    cvt_x_kernel<<<(MROWS * HID / 8) / 256, 256>>>(X);
    wtrans_kernel<<<dim3(HID / 32, HID / 32, 4), dim3(32, 8)>>>(Wq, Wk, Wv, Wo);

    dim3 gg(HID / 128, MROWS / 128, 3);
    qkv_gemm<<<gg, 256, GSMEM_BYTES>>>(bq, bk, bv);

    attn_kernel<<<dim3(SEQ / 128, NH, BATCH), 256, ASMEM_BYTES>>>();

    dim3 go(HID / 128, MROWS / 128);
    gemm_o<<<go, 256, GSMEM_BYTES>>>(bo, out);
}

// round 15
// speedup vs baseline: 8.4978x; 1.5733x over previous
#include <cuda_runtime.h>
#include <cuda_fp16.h>
#include <math.h>
#include <stdint.h>

#define BATCH 2
#define SEQ   2048
#define HID   2048
#define NH    16
#define HD    128
#define MROWS (BATCH*SEQ)   // 4096

// -------- scratch (static device globals, all half) ------------------------
__device__ __half g_qh[BATCH*NH*SEQ*HD];   // rope applied
__device__ __half g_kh[BATCH*NH*SEQ*HD];
__device__ __half g_vh[BATCH*NH*SEQ*HD];
__device__ __half g_atth[MROWS*HID];
__device__ __half g_xh[MROWS*HID];
__device__ __half g_wqT[HID*HID];          // W^T [N][K]
__device__ __half g_wkT[HID*HID];
__device__ __half g_wvT[HID*HID];
__device__ __half g_woT[HID*HID];
__device__ float  g_sin[SEQ*HD];
__device__ float  g_cos[SEQ*HD];

// -------- helpers ----------------------------------------------------------
__device__ __forceinline__ uint32_t smem_u32(const void* p) {
    uint32_t a;
    asm("{ .reg .u64 t; cvta.to.shared.u64 t, %1; cvt.u32.u64 %0, t; }"
        : "=r"(a) : "l"(p));
    return a;
}

__device__ __forceinline__ void cpa16(uint32_t dst, const void* src) {
    asm volatile(
        "{ .reg .u64 ga; cvta.to.global.u64 ga, %1;"
        "  cp.async.cg.shared.global [%0], [ga], 16; }"
        :: "r"(dst), "l"(src) : "memory");
}
__device__ __forceinline__ void cpa_commit() {
    asm volatile("cp.async.commit_group;" ::: "memory");
}
__device__ __forceinline__ void cpa_wait1() {
    asm volatile("cp.async.wait_group 1;" ::: "memory");
}

__device__ __forceinline__ void mma_f16(float* d, const unsigned* a, const unsigned* b) {
    asm volatile(
        "mma.sync.aligned.m16n8k16.row.col.f32.f16.f16.f32 "
        "{%0,%1,%2,%3}, {%4,%5,%6,%7}, {%8,%9}, {%0,%1,%2,%3};"
        : "+f"(d[0]), "+f"(d[1]), "+f"(d[2]), "+f"(d[3])
        : "r"(a[0]), "r"(a[1]), "r"(a[2]), "r"(a[3]), "r"(b[0]), "r"(b[1]));
}

__device__ __forceinline__ void ldsm4(unsigned* r, uint32_t addr) {
    asm volatile("ldmatrix.sync.aligned.m8n8.x4.shared.b16 {%0,%1,%2,%3}, [%4];"
        : "=r"(r[0]), "=r"(r[1]), "=r"(r[2]), "=r"(r[3]) : "r"(addr));
}
__device__ __forceinline__ void ldsm4t(unsigned* r, uint32_t addr) {
    asm volatile("ldmatrix.sync.aligned.m8n8.x4.trans.shared.b16 {%0,%1,%2,%3}, [%4];"
        : "=r"(r[0]), "=r"(r[1]), "=r"(r[2]), "=r"(r[3]) : "r"(addr));
}

// -------- RoPE table -------------------------------------------------------
__global__ void rope_table_kernel() {
    int idx = blockIdx.x * blockDim.x + threadIdx.x;
    if (idx >= SEQ*HD) return;
    int s = idx >> 7;
    int d = idx & 127;
    int j = d >> 1;
    float inv = (float)exp(-2.0 * (double)j / 128.0 * log(10000.0));
    float ang = (float)s * inv;
    g_sin[idx] = (float)sin((double)ang);
    g_cos[idx] = (float)cos((double)ang);
}

// -------- X -> half --------------------------------------------------------
__global__ void cvt_x_kernel(const float* __restrict__ X) {
    int i = (blockIdx.x * blockDim.x + threadIdx.x) * 8;
    float4 v0 = *(const float4*)(X + i);
    float4 v1 = *(const float4*)(X + i + 4);
    __half2 h[4];
    h[0] = __floats2half2_rn(v0.x, v0.y);
    h[1] = __floats2half2_rn(v0.z, v0.w);
    h[2] = __floats2half2_rn(v1.x, v1.y);
    h[3] = __floats2half2_rn(v1.z, v1.w);
    *(uint4*)(g_xh + i) = *(uint4*)h;
}

// -------- W [K][N] -> W^T [N][K] half, all 4 weights -----------------------
__global__ void wtrans_kernel(const float* __restrict__ Wq, const float* __restrict__ Wk,
                              const float* __restrict__ Wv, const float* __restrict__ Wo) {
    __shared__ float tile[32][33];
    const float* src; __half* dst;
    if (blockIdx.z == 0)      { src = Wq; dst = g_wqT; }
    else if (blockIdx.z == 1) { src = Wk; dst = g_wkT; }
    else if (blockIdx.z == 2) { src = Wv; dst = g_wvT; }
    else                      { src = Wo; dst = g_woT; }
    const int bx = blockIdx.x * 32;   // N
    const int by = blockIdx.y * 32;   // K
    const int tx = threadIdx.x, ty = threadIdx.y;
    #pragma unroll
    for (int j = 0; j < 32; j += 8)
        tile[ty + j][tx] = src[(size_t)(by + ty + j) * HID + bx + tx];
    __syncthreads();
    #pragma unroll
    for (int j = 0; j < 32; j += 8)
        dst[(size_t)(bx + ty + j) * HID + by + tx] = __float2half(tile[tx][ty + j]);
}

// -------- FP16 mma GEMM: C = A[M,K]@Bt[N,K]^T + bias -----------------------
// BK=64, 3-stage cp.async ring, fragment double-buffering.
#define AS_STRIDE 36                     // words per row (32 data + 4 pad)
#define A_WORDS (128*AS_STRIDE)          // 4608
#define STAGE_WORDS (2*A_WORDS)          // 9216
#define STAGE_BYTES (STAGE_WORDS*4)      // 36864
#define GSMEM_BYTES (3*STAGE_BYTES)      // 110592

__device__ __forceinline__ void gemm_body_h(
    const int mode,
    const __half* __restrict__ A, const __half* __restrict__ Bt,
    const float* __restrict__ bias, void* __restrict__ Cv,
    unsigned* smem, const int N, const int K)
{
    const uint32_t sbase = smem_u32(smem);
    const int t = threadIdx.x, wid = t >> 5, lane = t & 31;
    const int g = lane >> 2, c = lane & 3;
    const int wrow = wid >> 2, wcol = wid & 3;
    const int m0 = blockIdx.y * 128, n0 = blockIdx.x * 128;

    const int lm15  = lane & 15;
    const int lmsel = (lane & 16) ? 4 : 0;
    const int brow  = (lane & 7) + ((lane & 16) ? 8 : 0);
    const int bsel  = (lane & 8) ? 4 : 0;

    // loader: thread handles 4 chunks per tensor per stage; chunk s at row+32s
    const int lr = t >> 3, lq = t & 7;
    const __half* aP = A  + (size_t)(m0 + lr) * K + lq * 8;
    const __half* bP = Bt + (size_t)(n0 + lr) * K + lq * 8;
    const uint32_t aO = (lr * AS_STRIDE + lq * 4) * 4;
    const uint32_t bO = aO + A_WORDS * 4;
    const uint32_t chunkStride = 32 * AS_STRIDE * 4;   // +32 rows in smem

    float acc[4][4][4];
    #pragma unroll
    for (int i = 0; i < 4; i++)
        #pragma unroll
        for (int j = 0; j < 4; j++)
            #pragma unroll
            for (int r = 0; r < 4; r++) acc[i][j][r] = 0.0f;

    const int NIT = K >> 6;   // 32

    // prologue: stages 0,1
    #pragma unroll
    for (int p = 0; p < 2; p++) {
        uint32_t sb = sbase + p * STAGE_BYTES;
        #pragma unroll
        for (int s = 0; s < 4; s++) {
            cpa16(sb + aO + s * chunkStride, aP + p * 64 + (size_t)s * 32 * K);
            cpa16(sb + bO + s * chunkStride, bP + p * 64 + (size_t)s * 32 * K);
        }
        cpa_commit();
    }

    int rslot = 0, wslot = 2;
    for (int i = 0; i < NIT; i++) {
        cpa_wait1();
        __syncthreads();

        if (i + 2 < NIT) {
            uint32_t sb = sbase + wslot * STAGE_BYTES;
            #pragma unroll
            for (int s = 0; s < 4; s++) {
                cpa16(sb + aO + s * chunkStride, aP + (i + 2) * 64 + (size_t)s * 32 * K);
                cpa16(sb + bO + s * chunkStride, bP + (i + 2) * 64 + (size_t)s * 32 * K);
            }
        }
        cpa_commit();
        if (++wslot == 3) wslot = 0;

        const uint32_t sA = sbase + rslot * STAGE_BYTES;
        const uint32_t sB = sA + A_WORDS * 4;
        if (++rslot == 3) rslot = 0;

        // fragment double-buffer over 4 ksteps
        unsigned af[2][4][4], bf[2][2][4];
        #pragma unroll
        for (int mt = 0; mt < 4; mt++)
            ldsm4(af[0][mt], sA + ((wrow*64 + mt*16 + lm15) * AS_STRIDE + lmsel) * 4);
        #pragma unroll
        for (int np = 0; np < 2; np++)
            ldsm4(bf[0][np], sB + ((wcol*32 + np*16 + brow) * AS_STRIDE + bsel) * 4);

        #pragma unroll
        for (int ks = 0; ks < 4; ks++) {
            const int cur = ks & 1, nxt = cur ^ 1;
            if (ks < 3) {
                const int ko = (ks + 1) * 8;
                #pragma unroll
                for (int mt = 0; mt < 4; mt++)
                    ldsm4(af[nxt][mt], sA + ((wrow*64 + mt*16 + lm15) * AS_STRIDE + ko + lmsel) * 4);
                #pragma unroll
                for (int np = 0; np < 2; np++)
                    ldsm4(bf[nxt][np], sB + ((wcol*32 + np*16 + brow) * AS_STRIDE + ko + bsel) * 4);
            }
            #pragma unroll
            for (int np = 0; np < 2; np++)
                #pragma unroll
                for (int mt = 0; mt < 4; mt++) {
                    mma_f16(acc[mt][np*2 + 0], af[cur][mt], &bf[cur][np][0]);
                    mma_f16(acc[mt][np*2 + 1], af[cur][mt], &bf[cur][np][2]);
                }
        }
    }

    // Epilogue
    #pragma unroll
    for (int mt = 0; mt < 4; mt++) {
        #pragma unroll
        for (int nt = 0; nt < 4; nt++) {
            const int col = n0 + wcol * 32 + nt * 8 + 2 * c;
            #pragma unroll
            for (int half_ = 0; half_ < 2; half_++) {
                const int row = m0 + wrow * 64 + mt * 16 + g + half_ * 8;
                float v0 = acc[mt][nt][half_ * 2 + 0] + bias[col];
                float v1 = acc[mt][nt][half_ * 2 + 1] + bias[col + 1];
                if (mode == 0) {
                    float* C = (float*)Cv;
                    float2 o = make_float2(v0, v1);
                    *(float2*)(C + (size_t)row * N + col) = o;
                } else {
                    const int b = row >> 11;
                    const int s = row & (SEQ - 1);
                    const int h = col >> 7;
                    const int d = col & 127;
                    if (mode == 1) {
                        float sn = g_sin[s * HD + d];
                        float cs = g_cos[s * HD + d];
                        float o0 = v0 * cs - v1 * sn;
                        float o1 = v1 * cs + v0 * sn;
                        v0 = o0; v1 = o1;
                    }
                    size_t oidx = ((size_t)((b * NH + h) * SEQ + s)) * HD + d;
                    __half2 hv = __floats2half2_rn(v0, v1);
                    *(__half2*)((__half*)Cv + oidx) = hv;
                }
            }
        }
    }
}

__global__ __launch_bounds__(256, 2) void qkv_gemm(
    const float* __restrict__ bq, const float* __restrict__ bk,
    const float* __restrict__ bv)
{
    extern __shared__ unsigned smem[];
    const __half* Bt; const float* bias; __half* C; int mode;
    if (blockIdx.z == 0)      { Bt = g_wqT; bias = bq; C = g_qh; mode = 1; }
    else if (blockIdx.z == 1) { Bt = g_wkT; bias = bk; C = g_kh; mode = 1; }
    else                      { Bt = g_wvT; bias = bv; C = g_vh; mode = 2; }
    gemm_body_h(mode, g_xh, Bt, bias, C, smem, HID, HID);
}

__global__ __launch_bounds__(256, 2) void gemm_o(
    const float* __restrict__ bo, float* __restrict__ out)
{
    extern __shared__ unsigned smem[];
    gemm_body_h(0, g_atth, g_woT, bo, out, smem, HID, HID);
}

// -------- Flash attention fp16, FA2 layout: Br=128, Bc=64, 256 thr ---------
// (unchanged from round 14 — passing, register softmax)
#define ATQ  0                       // 8192 words
#define ATK  8192                    // 2 x 4096
#define ATV  16384                   // 2 x 4096
#define ATT_TOT 24576
#define ASMEM_BYTES (ATT_TOT * 4)    // 98304

__global__ __launch_bounds__(256, 2) void attn_kernel() {
    extern __shared__ unsigned sm[];
    const uint32_t sbase = smem_u32(sm);

    const int t = threadIdx.x, wid = t >> 5, lane = t & 31;
    const int g = lane >> 2, c = lane & 3;

    const int lm15  = lane & 15;
    const int lmsel = (lane & 16) ? 4 : 0;
    const int krow  = (lane & 7) + ((lane & 16) ? 8 : 0);
    const int ksel  = (lane & 8) ? 4 : 0;
    const int vsel  = (lane & 16) ? 4 : 0;
    const int lsw   = (lane & 7) << 2;

    const int q0 = blockIdx.x * 128;
    const int h  = blockIdx.y;
    const int b  = blockIdx.z;
    const size_t bh_off = (size_t)(b * NH + h) * SEQ * HD;
    const __half* qg = g_qh + bh_off;
    const __half* kg = g_kh + bh_off;
    const __half* vg = g_vh + bh_off;

    #pragma unroll
    for (int p = 0; p < 8; p++) {
        int lin = p * 256 + t;
        int r = lin >> 4, c4 = lin & 15;
        uint32_t swz = ((c4 * 4) ^ ((r & 7) << 2));
        cpa16(sbase + (ATQ + r * 64 + swz) * 4, qg + (size_t)(q0 + r) * HD + c4 * 8);
    }
    #pragma unroll
    for (int p = 0; p < 4; p++) {
        int lin = p * 256 + t;
        int r = lin >> 4, c4 = lin & 15;
        uint32_t swz = ((c4 * 4) ^ ((r & 7) << 2));
        cpa16(sbase + (ATK + r * 64 + swz) * 4, kg + (size_t)r * HD + c4 * 8);
        cpa16(sbase + (ATV + r * 64 + swz) * 4, vg + (size_t)r * HD + c4 * 8);
    }
    cpa_commit();
    #pragma unroll
    for (int p = 0; p < 4; p++) {
        int lin = p * 256 + t;
        int r = lin >> 4, c4 = lin & 15;
        uint32_t swz = ((c4 * 4) ^ ((r & 7) << 2));
        cpa16(sbase + (ATK + 4096 + r * 64 + swz) * 4, kg + (size_t)(64 + r) * HD + c4 * 8);
        cpa16(sbase + (ATV + 4096 + r * 64 + swz) * 4, vg + (size_t)(64 + r) * HD + c4 * 8);
    }
    cpa_commit();

    float m0 = -INFINITY, m1 = -INFINITY;
    float l0 = 0.0f, l1 = 0.0f;

    float oacc[16][4];
    #pragma unroll
    for (int i = 0; i < 16; i++)
        #pragma unroll
        for (int r = 0; r < 4; r++) oacc[i][r] = 0.0f;

    const float scale = 0.08838834764831845f;
    const uint32_t qrow_base = sbase + (ATQ + (wid * 16 + lm15) * 64) * 4;

    for (int it = 0; it < SEQ / 64; it++) {
        cpa_wait1();
        __syncthreads();
        const uint32_t kbb = sbase + (ATK + (it & 1) * 4096) * 4;
        const uint32_t vbb = sbase + (ATV + (it & 1) * 4096) * 4;

        float sacc[8][4];
        #pragma unroll
        for (int i = 0; i < 8; i++)
            #pragma unroll
            for (int r = 0; r < 4; r++) sacc[i][r] = 0.0f;

        #pragma unroll 4
        for (int ks = 0; ks < 8; ks++) {
            unsigned aq[4];
            ldsm4(aq, qrow_base + (((ks * 8 + lmsel) ^ lsw)) * 4);
            #pragma unroll
            for (int nn = 0; nn < 4; nn++) {
                unsigned bk2[4];
                ldsm4(bk2, kbb + ((nn * 16 + krow) * 64 + ((ks * 8 + ksel) ^ lsw)) * 4);
                mma_f16(sacc[nn * 2 + 0], aq, &bk2[0]);
                mma_f16(sacc[nn * 2 + 1], aq, &bk2[2]);
            }
        }

        float mx0 = -INFINITY, mx1 = -INFINITY;
        #pragma unroll
        for (int nt = 0; nt < 8; nt++) {
            mx0 = fmaxf(mx0, fmaxf(sacc[nt][0], sacc[nt][1]));
            mx1 = fmaxf(mx1, fmaxf(sacc[nt][2], sacc[nt][3]));
        }
        mx0 = fmaxf(mx0, __shfl_xor_sync(0xffffffffu, mx0, 1));
        mx0 = fmaxf(mx0, __shfl_xor_sync(0xffffffffu, mx0, 2));
        mx1 = fmaxf(mx1, __shfl_xor_sync(0xffffffffu, mx1, 1));
        mx1 = fmaxf(mx1, __shfl_xor_sync(0xffffffffu, mx1, 2));
        const float mn0 = fmaxf(m0, mx0 * scale);
        const float mn1 = fmaxf(m1, mx1 * scale);
        const float f0 = __expf(m0 - mn0);
        const float f1 = __expf(m1 - mn1);
        float ps0 = 0.0f, ps1 = 0.0f;
        #pragma unroll
        for (int nt = 0; nt < 8; nt++) {
            sacc[nt][0] = __expf(sacc[nt][0] * scale - mn0);
            sacc[nt][1] = __expf(sacc[nt][1] * scale - mn0);
            sacc[nt][2] = __expf(sacc[nt][2] * scale - mn1);
            sacc[nt][3] = __expf(sacc[nt][3] * scale - mn1);
            ps0 += sacc[nt][0] + sacc[nt][1];
            ps1 += sacc[nt][2] + sacc[nt][3];
        }
        ps0 += __shfl_xor_sync(0xffffffffu, ps0, 1);
        ps0 += __shfl_xor_sync(0xffffffffu, ps0, 2);
        ps1 += __shfl_xor_sync(0xffffffffu, ps1, 1);
        ps1 += __shfl_xor_sync(0xffffffffu, ps1, 2);
        l0 = l0 * f0 + ps0;  m0 = mn0;
        l1 = l1 * f1 + ps1;  m1 = mn1;

        unsigned pa[4][4];
        #pragma unroll
        for (int ks = 0; ks < 4; ks++) {
            __half2 h0 = __floats2half2_rn(sacc[2*ks][0],   sacc[2*ks][1]);
            __half2 h1 = __floats2half2_rn(sacc[2*ks][2],   sacc[2*ks][3]);
            __half2 h2 = __floats2half2_rn(sacc[2*ks+1][0], sacc[2*ks+1][1]);
            __half2 h3 = __floats2half2_rn(sacc[2*ks+1][2], sacc[2*ks+1][3]);
            pa[ks][0] = *(unsigned*)&h0;
            pa[ks][1] = *(unsigned*)&h1;
            pa[ks][2] = *(unsigned*)&h2;
            pa[ks][3] = *(unsigned*)&h3;
        }
        #pragma unroll
        for (int nt = 0; nt < 16; nt++) {
            oacc[nt][0] *= f0; oacc[nt][1] *= f0;
            oacc[nt][2] *= f1; oacc[nt][3] *= f1;
        }

        #pragma unroll
        for (int ks = 0; ks < 4; ks++) {
            #pragma unroll
            for (int nn = 0; nn < 8; nn++) {
                unsigned bv2[4];
                ldsm4t(bv2, vbb + ((ks * 16 + lm15) * 64 + ((nn * 8 + vsel) ^ lsw)) * 4);
                mma_f16(oacc[nn * 2 + 0], pa[ks], &bv2[0]);
                mma_f16(oacc[nn * 2 + 1], pa[ks], &bv2[2]);
            }
        }
        __syncthreads();

        if (it + 2 < SEQ / 64) {
            const int nxt = (it + 2) * 64;
            const uint32_t kd = ATK + (it & 1) * 4096;
            const uint32_t vd = ATV + (it & 1) * 4096;
            #pragma unroll
            for (int p = 0; p < 4; p++) {
                int lin = p * 256 + t;
                int r = lin >> 4, c4 = lin & 15;
                uint32_t swz = ((c4 * 4) ^ ((r & 7) << 2));
                cpa16(sbase + (kd + r * 64 + swz) * 4, kg + (size_t)(nxt + r) * HD + c4 * 8);
                cpa16(sbase + (vd + r * 64 + swz) * 4, vg + (size_t)(nxt + r) * HD + c4 * 8);
            }
            cpa_commit();
        }
    }

    const float il0 = 1.0f / l0;
    const float il1 = 1.0f / l1;
    const int r0 = wid * 16 + g;
    #pragma unroll
    for (int nt = 0; nt < 16; nt++) {
        const int col = nt * 8 + 2 * c;
        size_t base0 = ((size_t)(b * SEQ + q0 + r0)) * HID + h * HD + col;
        size_t base1 = base0 + (size_t)8 * HID;
        __half2 h0 = __floats2half2_rn(oacc[nt][0] * il0, oacc[nt][1] * il0);
        __half2 h1 = __floats2half2_rn(oacc[nt][2] * il1, oacc[nt][3] * il1);
        *(__half2*)(g_atth + base0) = h0;
        *(__half2*)(g_atth + base1) = h1;
    }
}

// ---------------------------------------------------------------------------
extern "C" void kernel_launch(void* const* d_in, const int* in_sizes, int n_in,
                              void* d_out, int out_size) {
    const float* X  = (const float*)d_in[0];
    const float* Wq = (const float*)d_in[1];
    const float* bq = (const float*)d_in[2];
    const float* Wk = (const float*)d_in[3];
    const float* bk = (const float*)d_in[4];
    const float* Wv = (const float*)d_in[5];
    const float* bv = (const float*)d_in[6];
    const float* Wo = (const float*)d_in[7];
    const float* bo = (const float*)d_in[8];
    float* out = (float*)d_out;

    cudaFuncSetAttribute(attn_kernel,
                         cudaFuncAttributeMaxDynamicSharedMemorySize, ASMEM_BYTES);
    cudaFuncSetAttribute(qkv_gemm,
                         cudaFuncAttributeMaxDynamicSharedMemorySize, GSMEM_BYTES);
    cudaFuncSetAttribute(gemm_o,
                         cudaFuncAttributeMaxDynamicSharedMemorySize, GSMEM_BYTES);

    rope_table_kernel<<<(SEQ * HD) / 256, 256>>>();
    cvt_x_kernel<<<(MROWS * HID / 8) / 256, 256>>>(X);
    wtrans_kernel<<<dim3(HID / 32, HID / 32, 4), dim3(32, 8)>>>(Wq, Wk, Wv, Wo);

    dim3 gg(HID / 128, MROWS / 128, 3);
    qkv_gemm<<<gg, 256, GSMEM_BYTES>>>(bq, bk, bv);

    attn_kernel<<<dim3(SEQ / 128, NH, BATCH), 256, ASMEM_BYTES>>>();

    dim3 go(HID / 128, MROWS / 128);
    gemm_o<<<go, 256, GSMEM_BYTES>>>(bo, out);
}